// round 2
// baseline (speedup 1.0000x reference)
#include <cuda_runtime.h>

// Problem: out[16384,1280] = x[16384,1280] @ A[1280,1280]
// where A = (k1 (x) k2 (x) k3) @ W^T, computed via factored Kronecker application.
//
// d_in order (metadata): x [4,4096,1280] f32, W [1280,1280] f32,
//                        kron_1 [4,4] f32, kron_2 [8,8] f32, kron_3 [40,40] f32
// out: f32, 16384*1280

#define DD 1280
#define MROWS 16384

// Scratch (allocation-free rule: __device__ globals). Ping-pong between the two.
__device__ float g_buf0[DD * DD];
__device__ float g_buf1[DD * DD];

// ---------------------------------------------------------------------------
// Wt[j][o] = W[o][j]   (so all later stages read row-major, coalesced over o)
// ---------------------------------------------------------------------------
__global__ void transpose_kernel(const float* __restrict__ W, float* __restrict__ Wt) {
    __shared__ float tile[32][33];
    const int j0 = blockIdx.x * 32;
    const int o0 = blockIdx.y * 32;
    const int tx = threadIdx.x, ty = threadIdx.y;
#pragma unroll
    for (int r = 0; r < 32; r += 8)
        tile[ty + r][tx] = W[(o0 + ty + r) * DD + (j0 + tx)];
    __syncthreads();
#pragma unroll
    for (int r = 0; r < 32; r += 8)
        Wt[(j0 + ty + r) * DD + (o0 + tx)] = tile[tx][ty + r];
}

// ---------------------------------------------------------------------------
// Stage 3: T1[(g*40 + a3)][o] = sum_{b3<40} k3[a3][b3] * Wt[(g*40 + b3)][o]
//   g = (b1*8 + b2) in [0,32)
// ---------------------------------------------------------------------------
__global__ void stage3_kernel(const float* __restrict__ src, float* __restrict__ dst,
                              const float* __restrict__ k3) {
    const int o = blockIdx.x * 256 + threadIdx.x;
    const int i = blockIdx.y;                 // 0..1279
    const int g = i / 40;
    const int a3 = i % 40;

    __shared__ float krow[40];
    if (threadIdx.x < 40) krow[threadIdx.x] = k3[a3 * 40 + threadIdx.x];
    __syncthreads();

    const float* s = src + (g * 40) * DD + o;
    float acc = 0.f;
#pragma unroll 8
    for (int b3 = 0; b3 < 40; b3++)
        acc += krow[b3] * s[b3 * DD];
    dst[i * DD + o] = acc;
}

// ---------------------------------------------------------------------------
// Stage 2: T2[((b1*8 + a2)*40 + a3)][o] = sum_{b2<8} k2[a2][b2] * T1[((b1*8+b2)*40+a3)][o]
// ---------------------------------------------------------------------------
__global__ void stage2_kernel(const float* __restrict__ src, float* __restrict__ dst,
                              const float* __restrict__ k2) {
    const int o = blockIdx.x * 256 + threadIdx.x;
    const int i = blockIdx.y;
    const int b1 = i / 320;
    const int a2 = (i / 40) % 8;
    const int a3 = i % 40;

    const float* s = src + ((b1 * 8) * 40 + a3) * DD + o;
    float acc = 0.f;
#pragma unroll
    for (int b2 = 0; b2 < 8; b2++)
        acc += __ldg(&k2[a2 * 8 + b2]) * s[b2 * 40 * DD];
    dst[i * DD + o] = acc;
}

// ---------------------------------------------------------------------------
// Stage 1: A[((a1*8 + a2)*40 + a3)][o] = sum_{b1<4} k1[a1][b1] * T2[(b1*320 + rem)][o]
// ---------------------------------------------------------------------------
__global__ void stage1_kernel(const float* __restrict__ src, float* __restrict__ dst,
                              const float* __restrict__ k1) {
    const int o = blockIdx.x * 256 + threadIdx.x;
    const int i = blockIdx.y;
    const int a1 = i / 320;
    const int rem = i % 320;

    const float* s = src + rem * DD + o;
    float acc = 0.f;
#pragma unroll
    for (int b1 = 0; b1 < 4; b1++)
        acc += __ldg(&k1[a1 * 4 + b1]) * s[b1 * 320 * DD];
    dst[i * DD + o] = acc;
}

// ---------------------------------------------------------------------------
// Main SGEMM: out[M,N] = X[M,K] @ A[K,N], M=16384, N=K=1280
// 128x128 tile, BK=8, 256 threads, 8x8 per thread, vectorized smem access.
// ---------------------------------------------------------------------------
#define BM 128
#define BN 128
#define BK 8
#define TM 8
#define TN 8

__global__ __launch_bounds__(256, 2)
void sgemm_kernel(const float* __restrict__ X, const float* __restrict__ A,
                  float* __restrict__ out) {
    const int K = DD, N = DD;
    const int bm = blockIdx.y, bn = blockIdx.x;

    __shared__ __align__(16) float As[BK][BM];  // transposed x tile
    __shared__ __align__(16) float Bs[BK][BN];

    const int tid = threadIdx.x;

    // global->smem load indices
    const int aRow  = tid >> 1;          // 0..127
    const int aCol4 = (tid & 1) * 4;     // 0 or 4
    const int bRow  = tid >> 5;          // 0..7
    const int bCol4 = (tid & 31) * 4;    // 0..124

    const float* Xp = X + (bm * BM + aRow) * K + aCol4;
    const float* Ap = A + bRow * N + bn * BN + bCol4;

    const int tx = tid & 15;             // 0..15 -> col group
    const int ty = tid >> 4;             // 0..15 -> row group

    float acc[TM][TN];
#pragma unroll
    for (int i = 0; i < TM; i++)
#pragma unroll
        for (int j = 0; j < TN; j++) acc[i][j] = 0.f;

    for (int k0 = 0; k0 < K; k0 += BK) {
        float4 xa = *reinterpret_cast<const float4*>(Xp);
        float4 bb = *reinterpret_cast<const float4*>(Ap);
        Xp += BK;
        Ap += BK * N;

        As[aCol4 + 0][aRow] = xa.x;
        As[aCol4 + 1][aRow] = xa.y;
        As[aCol4 + 2][aRow] = xa.z;
        As[aCol4 + 3][aRow] = xa.w;
        *reinterpret_cast<float4*>(&Bs[bRow][bCol4]) = bb;
        __syncthreads();

#pragma unroll
        for (int k = 0; k < BK; k++) {
            float4 rm0 = *reinterpret_cast<const float4*>(&As[k][ty * TM]);
            float4 rm1 = *reinterpret_cast<const float4*>(&As[k][ty * TM + 4]);
            float4 rn0 = *reinterpret_cast<const float4*>(&Bs[k][tx * TN]);
            float4 rn1 = *reinterpret_cast<const float4*>(&Bs[k][tx * TN + 4]);
            float rm[TM] = {rm0.x, rm0.y, rm0.z, rm0.w, rm1.x, rm1.y, rm1.z, rm1.w};
            float rn[TN] = {rn0.x, rn0.y, rn0.z, rn0.w, rn1.x, rn1.y, rn1.z, rn1.w};
#pragma unroll
            for (int i = 0; i < TM; i++)
#pragma unroll
                for (int j = 0; j < TN; j++)
                    acc[i][j] = fmaf(rm[i], rn[j], acc[i][j]);
        }
        __syncthreads();
    }

    float* op = out + (bm * BM + ty * TM) * N + bn * BN + tx * TN;
#pragma unroll
    for (int i = 0; i < TM; i++) {
        float4 v0 = make_float4(acc[i][0], acc[i][1], acc[i][2], acc[i][3]);
        float4 v1 = make_float4(acc[i][4], acc[i][5], acc[i][6], acc[i][7]);
        *reinterpret_cast<float4*>(op + i * N + 0) = v0;
        *reinterpret_cast<float4*>(op + i * N + 4) = v1;
    }
}

// ---------------------------------------------------------------------------
extern "C" void kernel_launch(void* const* d_in, const int* in_sizes, int n_in,
                              void* d_out, int out_size) {
    const float* x  = (const float*)d_in[0];
    const float* W  = (const float*)d_in[1];
    const float* k1 = (const float*)d_in[2];
    const float* k2 = (const float*)d_in[3];
    const float* k3 = (const float*)d_in[4];
    float* out = (float*)d_out;

    float* buf0;
    float* buf1;
    cudaGetSymbolAddress((void**)&buf0, g_buf0);
    cudaGetSymbolAddress((void**)&buf1, g_buf1);

    // Wt = W^T into buf0
    {
        dim3 grid(DD / 32, DD / 32), block(32, 8);
        transpose_kernel<<<grid, block>>>(W, buf0);
    }
    // Kron application: buf0 -> buf1 -> buf0 -> buf1 (= A)
    {
        dim3 grid(DD / 256, DD), block(256);
        stage3_kernel<<<grid, block>>>(buf0, buf1, k3);
        stage2_kernel<<<grid, block>>>(buf1, buf0, k2);
        stage1_kernel<<<grid, block>>>(buf0, buf1, k1);
    }
    // out = x @ A
    {
        dim3 grid(DD / BN, MROWS / BM), block(256);
        sgemm_kernel<<<grid, block>>>(x, buf1, out);
    }
}

// round 4
// speedup vs baseline: 2.0934x; 2.0934x over previous
#include <cuda_runtime.h>
#include <cuda_bf16.h>
#include <cstdint>

// out[16384,1280] = x[16384,1280] @ A[1280,1280],  A = (k1 (x) k2 (x) k3) @ W^T
// Kron factorization in fp32, then split-precision bf16 HMMA GEMM:
//   D = Xhi*Ahi + Xhi*Alo + Xlo*Ahi   (fp32 accumulate, XloAlo term ~2^-18 dropped)
// NOTE: harness device pass targets compute_103 (no 'a') -> tcgen05 unavailable;
// mma.sync.m16n8k16 (baseline PTX, sm_80+) is the tensor path that compiles.

#define DD 1280
#define MROWS 16384

__device__ float g_buf0[DD * DD];
__device__ float g_buf1[DD * DD];
__device__ __nv_bfloat16 g_Xhi[(size_t)MROWS * DD];
__device__ __nv_bfloat16 g_Xlo[(size_t)MROWS * DD];
__device__ __nv_bfloat16 g_Athi[DD * DD];   // A^T: [n][k], k contiguous
__device__ __nv_bfloat16 g_Atlo[DD * DD];

// ---------------------------------------------------------------------------
__device__ __forceinline__ uint32_t smem_u32(const void* p) {
    uint32_t a;
    asm("{ .reg .u64 t; cvta.to.shared.u64 t, %1; cvt.u32.u64 %0, t; }" : "=r"(a) : "l"(p));
    return a;
}
__device__ __forceinline__ void ldsm_x4(uint32_t* r, uint32_t addr) {
    asm volatile("ldmatrix.sync.aligned.m8n8.x4.shared.b16 {%0,%1,%2,%3}, [%4];"
                 : "=r"(r[0]), "=r"(r[1]), "=r"(r[2]), "=r"(r[3]) : "r"(addr));
}
__device__ __forceinline__ void mma_bf16(float* c, const uint32_t* a, const uint32_t* b) {
    asm volatile("mma.sync.aligned.m16n8k16.row.col.f32.bf16.bf16.f32 "
                 "{%0,%1,%2,%3}, {%4,%5,%6,%7}, {%8,%9}, {%0,%1,%2,%3};"
                 : "+f"(c[0]), "+f"(c[1]), "+f"(c[2]), "+f"(c[3])
                 : "r"(a[0]), "r"(a[1]), "r"(a[2]), "r"(a[3]), "r"(b[0]), "r"(b[1]));
}
#define CP16(dst, src) \
    asm volatile("cp.async.cg.shared.global [%0], [%1], 16;" :: "r"(dst), "l"(src))
#define CP_COMMIT() asm volatile("cp.async.commit_group;" ::: "memory")
#define CP_WAIT1()  asm volatile("cp.async.wait_group 1;" ::: "memory")

// ---------------------------------------------------------------------------
// Prologue chain (fp32): W^T, Kron stages, splits
// ---------------------------------------------------------------------------
__global__ void transpose_kernel(const float* __restrict__ W, float* __restrict__ Wt) {
    __shared__ float tile[32][33];
    const int j0 = blockIdx.x * 32, o0 = blockIdx.y * 32;
    const int tx = threadIdx.x, ty = threadIdx.y;
#pragma unroll
    for (int r = 0; r < 32; r += 8)
        tile[ty + r][tx] = W[(o0 + ty + r) * DD + (j0 + tx)];
    __syncthreads();
#pragma unroll
    for (int r = 0; r < 32; r += 8)
        Wt[(j0 + ty + r) * DD + (o0 + tx)] = tile[tx][ty + r];
}
__global__ void stage3_kernel(const float* __restrict__ src, float* __restrict__ dst,
                              const float* __restrict__ k3) {
    const int o = blockIdx.x * 256 + threadIdx.x;
    const int i = blockIdx.y;
    const int g = i / 40, a3 = i % 40;
    __shared__ float krow[40];
    if (threadIdx.x < 40) krow[threadIdx.x] = k3[a3 * 40 + threadIdx.x];
    __syncthreads();
    const float* s = src + (g * 40) * DD + o;
    float acc = 0.f;
#pragma unroll 8
    for (int b3 = 0; b3 < 40; b3++) acc += krow[b3] * s[b3 * DD];
    dst[i * DD + o] = acc;
}
__global__ void stage2_kernel(const float* __restrict__ src, float* __restrict__ dst,
                              const float* __restrict__ k2) {
    const int o = blockIdx.x * 256 + threadIdx.x;
    const int i = blockIdx.y;
    const int b1 = i / 320, a2 = (i / 40) % 8, a3 = i % 40;
    const float* s = src + ((b1 * 8) * 40 + a3) * DD + o;
    float acc = 0.f;
#pragma unroll
    for (int b2 = 0; b2 < 8; b2++) acc += __ldg(&k2[a2 * 8 + b2]) * s[b2 * 40 * DD];
    dst[i * DD + o] = acc;
}
__global__ void stage1_kernel(const float* __restrict__ src, float* __restrict__ dst,
                              const float* __restrict__ k1) {
    const int o = blockIdx.x * 256 + threadIdx.x;
    const int i = blockIdx.y;
    const int a1 = i / 320, rem = i % 320;
    const float* s = src + rem * DD + o;
    float acc = 0.f;
#pragma unroll
    for (int b1 = 0; b1 < 4; b1++) acc += __ldg(&k1[a1 * 4 + b1]) * s[b1 * 320 * DD];
    dst[i * DD + o] = acc;
}
__global__ void split_x_kernel(const float* __restrict__ x,
                               __nv_bfloat16* __restrict__ xhi,
                               __nv_bfloat16* __restrict__ xlo) {
    const size_t i4 = ((size_t)blockIdx.x * 256 + threadIdx.x) * 4;
    float4 v = *reinterpret_cast<const float4*>(x + i4);
    float vv[4] = {v.x, v.y, v.z, v.w};
    unsigned short h[4], l[4];
#pragma unroll
    for (int j = 0; j < 4; j++) {
        __nv_bfloat16 hb = __float2bfloat16_rn(vv[j]);
        float r = vv[j] - __bfloat162float(hb);
        h[j] = __bfloat16_as_ushort(hb);
        l[j] = __bfloat16_as_ushort(__float2bfloat16_rn(r));
    }
    uint2 hv, lv;
    hv.x = (uint32_t)h[0] | ((uint32_t)h[1] << 16);
    hv.y = (uint32_t)h[2] | ((uint32_t)h[3] << 16);
    lv.x = (uint32_t)l[0] | ((uint32_t)l[1] << 16);
    lv.y = (uint32_t)l[2] | ((uint32_t)l[3] << 16);
    *reinterpret_cast<uint2*>(xhi + i4) = hv;
    *reinterpret_cast<uint2*>(xlo + i4) = lv;
}
__global__ void split_at_kernel(const float* __restrict__ A,
                                __nv_bfloat16* __restrict__ athi,
                                __nv_bfloat16* __restrict__ atlo) {
    __shared__ float t[32][33];
    const int k0 = blockIdx.x * 32, n0 = blockIdx.y * 32;
    const int tx = threadIdx.x, ty = threadIdx.y;
#pragma unroll
    for (int r = 0; r < 32; r += 8)
        t[ty + r][tx] = A[(k0 + ty + r) * DD + (n0 + tx)];
    __syncthreads();
#pragma unroll
    for (int r = 0; r < 32; r += 8) {
        float v = t[tx][ty + r];
        __nv_bfloat16 hb = __float2bfloat16_rn(v);
        float rr = v - __bfloat162float(hb);
        athi[(n0 + ty + r) * DD + (k0 + tx)] = hb;
        atlo[(n0 + ty + r) * DD + (k0 + tx)] = __float2bfloat16_rn(rr);
    }
}

// ---------------------------------------------------------------------------
// HMMA split-bf16 GEMM. CTA tile 128x128, BK=32, 256 threads, 3-stage cp.async.
// smem tiles padded: 40 bf16/row (80 B) -> conflict-free ldmatrix.
// ---------------------------------------------------------------------------
#define BK 32
#define PADK 40
#define XTB (128 * PADK * 2)        // 10240 B per tile
#define STB (4 * XTB)               // stage: Xhi, Xlo, Ahi, Alo = 40960 B
#define NSTAGE 3
#define GEMM_SMEM (NSTAGE * STB)    // 122880 B
#define KTILES (DD / BK)            // 40

__device__ __forceinline__ void load_stage_async(
    uint32_t sdst,
    const __nv_bfloat16* __restrict__ Xhi, const __nv_bfloat16* __restrict__ Xlo,
    const __nv_bfloat16* __restrict__ Ahi, const __nv_bfloat16* __restrict__ Alo,
    int bm, int bn, int kt, int tid) {
    const int kofs = kt * BK;
#pragma unroll
    for (int i = 0; i < 2; i++) {
        int idx = i * 256 + tid;          // 0..511
        int row = idx >> 2, c = idx & 3;  // 4 x 16B chunks per 64B row
        uint32_t so = (uint32_t)(row * (PADK * 2) + c * 16);
        size_t gx = (size_t)(bm * 128 + row) * DD + kofs + c * 8;
        size_t ga = (size_t)(bn * 128 + row) * DD + kofs + c * 8;
        CP16(sdst + so,           Xhi + gx);
        CP16(sdst + XTB + so,     Xlo + gx);
        CP16(sdst + 2 * XTB + so, Ahi + ga);
        CP16(sdst + 3 * XTB + so, Alo + ga);
    }
}

__global__ __launch_bounds__(256, 1)
void gemm_hmma_kernel(const __nv_bfloat16* __restrict__ Xhi,
                      const __nv_bfloat16* __restrict__ Xlo,
                      const __nv_bfloat16* __restrict__ Athi,
                      const __nv_bfloat16* __restrict__ Atlo,
                      float* __restrict__ out) {
    extern __shared__ __align__(128) char smem[];
    const uint32_t sbase = smem_u32(smem);
    const int tid = threadIdx.x, lane = tid & 31, wid = tid >> 5;
    const int warp_m = wid & 3, warp_n = wid >> 2;   // 4 x 2 warps, tile 32x64
    const int bn = blockIdx.x, bm = blockIdx.y;

    float acc[2][8][4];
#pragma unroll
    for (int a = 0; a < 2; a++)
#pragma unroll
        for (int b = 0; b < 8; b++)
#pragma unroll
            for (int c = 0; c < 4; c++) acc[a][b][c] = 0.f;

    load_stage_async(sbase, Xhi, Xlo, Athi, Atlo, bm, bn, 0, tid);
    CP_COMMIT();
    load_stage_async(sbase + STB, Xhi, Xlo, Athi, Atlo, bm, bn, 1, tid);
    CP_COMMIT();

    // per-thread ldmatrix lane addressing (byte offsets within a tile)
    const uint32_t a_row = (uint32_t)(warp_m * 32 + (lane & 7) + ((lane >> 3) & 1) * 8);
    const uint32_t a_colb = (uint32_t)(((lane >> 4) & 1) * 8) * 2;
    const uint32_t b_nrow = (uint32_t)(warp_n * 64 + (lane & 7) + ((lane >> 4) & 1) * 8);
    const uint32_t b_kb = (uint32_t)(((lane >> 3) & 1) * 8) * 2;

    for (int kt = 0; kt < KTILES; kt++) {
        CP_WAIT1();
        __syncthreads();
        const uint32_t st = sbase + (uint32_t)(kt % NSTAGE) * STB;
        const uint32_t sXh = st, sXl = st + XTB, sAh = st + 2 * XTB, sAl = st + 3 * XTB;
#pragma unroll
        for (int kk = 0; kk < 2; kk++) {
            const uint32_t acol = a_colb + kk * 32;   // kk*16 elems * 2B
            const uint32_t bcol = b_kb + kk * 32;
            uint32_t ah[2][4], al[2][4];
            ldsm_x4(ah[0], sXh + a_row * (PADK * 2) + acol);
            ldsm_x4(ah[1], sXh + (a_row + 16) * (PADK * 2) + acol);
            ldsm_x4(al[0], sXl + a_row * (PADK * 2) + acol);
            ldsm_x4(al[1], sXl + (a_row + 16) * (PADK * 2) + acol);
            uint32_t bh[8][2], bl[8][2];
#pragma unroll
            for (int j = 0; j < 4; j++) {
                uint32_t r[4];
                ldsm_x4(r, sAh + (b_nrow + j * 16) * (PADK * 2) + bcol);
                bh[2 * j][0] = r[0]; bh[2 * j][1] = r[1];
                bh[2 * j + 1][0] = r[2]; bh[2 * j + 1][1] = r[3];
                ldsm_x4(r, sAl + (b_nrow + j * 16) * (PADK * 2) + bcol);
                bl[2 * j][0] = r[0]; bl[2 * j][1] = r[1];
                bl[2 * j + 1][0] = r[2]; bl[2 * j + 1][1] = r[3];
            }
#pragma unroll
            for (int mi = 0; mi < 2; mi++)
#pragma unroll
                for (int nt = 0; nt < 8; nt++) {
                    mma_bf16(acc[mi][nt], ah[mi], bh[nt]);
                    mma_bf16(acc[mi][nt], ah[mi], bl[nt]);
                    mma_bf16(acc[mi][nt], al[mi], bh[nt]);
                }
        }
        __syncthreads();
        if (kt + 2 < KTILES)
            load_stage_async(sbase + (uint32_t)((kt + 2) % NSTAGE) * STB,
                             Xhi, Xlo, Athi, Atlo, bm, bn, kt + 2, tid);
        CP_COMMIT();
    }

    // epilogue
    const int er = lane >> 2, ec = (lane & 3) * 2;
#pragma unroll
    for (int mi = 0; mi < 2; mi++) {
        const int row = bm * 128 + warp_m * 32 + mi * 16 + er;
#pragma unroll
        for (int nt = 0; nt < 8; nt++) {
            const int col = bn * 128 + warp_n * 64 + nt * 8 + ec;
            *reinterpret_cast<float2*>(out + (size_t)row * DD + col) =
                make_float2(acc[mi][nt][0], acc[mi][nt][1]);
            *reinterpret_cast<float2*>(out + (size_t)(row + 8) * DD + col) =
                make_float2(acc[mi][nt][2], acc[mi][nt][3]);
        }
    }
}

// ---------------------------------------------------------------------------
extern "C" void kernel_launch(void* const* d_in, const int* in_sizes, int n_in,
                              void* d_out, int out_size) {
    const float* x  = (const float*)d_in[0];
    const float* W  = (const float*)d_in[1];
    const float* k1 = (const float*)d_in[2];
    const float* k2 = (const float*)d_in[3];
    const float* k3 = (const float*)d_in[4];
    float* out = (float*)d_out;

    float *buf0, *buf1;
    __nv_bfloat16 *xhi, *xlo, *athi, *atlo;
    cudaGetSymbolAddress((void**)&buf0, g_buf0);
    cudaGetSymbolAddress((void**)&buf1, g_buf1);
    cudaGetSymbolAddress((void**)&xhi, g_Xhi);
    cudaGetSymbolAddress((void**)&xlo, g_Xlo);
    cudaGetSymbolAddress((void**)&athi, g_Athi);
    cudaGetSymbolAddress((void**)&atlo, g_Atlo);

    {
        size_t n4 = (size_t)MROWS * DD / 4;
        split_x_kernel<<<(unsigned)(n4 / 256), 256>>>(x, xhi, xlo);
    }
    {
        dim3 grid(DD / 32, DD / 32), block(32, 8);
        transpose_kernel<<<grid, block>>>(W, buf0);
    }
    {
        dim3 grid(DD / 256, DD), block(256);
        stage3_kernel<<<grid, block>>>(buf0, buf1, k3);
        stage2_kernel<<<grid, block>>>(buf1, buf0, k2);
        stage1_kernel<<<grid, block>>>(buf0, buf1, k1);
    }
    {
        dim3 grid(DD / 32, DD / 32), block(32, 8);
        split_at_kernel<<<grid, block>>>(buf1, athi, atlo);
    }
    {
        static bool attr_set = false;
        if (!attr_set) {
            cudaFuncSetAttribute(gemm_hmma_kernel,
                                 cudaFuncAttributeMaxDynamicSharedMemorySize, GEMM_SMEM);
            attr_set = true;
        }
        dim3 grid(DD / 128, MROWS / 128);   // (10, 128)
        gemm_hmma_kernel<<<grid, 256, GEMM_SMEM>>>(xhi, xlo, athi, atlo, out);
    }
}

// round 5
// speedup vs baseline: 2.5789x; 1.2320x over previous
#include <cuda_runtime.h>
#include <cuda_bf16.h>
#include <cstdint>

// out[16384,1280] = x[16384,1280] @ A[1280,1280],  A = (k1 (x) k2 (x) k3) @ W^T
// Kron factorization in fp32, then split-precision bf16 HMMA GEMM:
//   D = Xhi*Ahi + Xhi*Alo + Xlo*Ahi   (fp32 accumulate, XloAlo term ~2^-18 dropped)
// R4: 2 CTAs/SM (NSTAGE=2, 80KB smem, <=128 regs), B-fragments in halves.

#define DD 1280
#define MROWS 16384

__device__ float g_buf0[DD * DD];
__device__ float g_buf1[DD * DD];
__device__ __nv_bfloat16 g_Xhi[(size_t)MROWS * DD];
__device__ __nv_bfloat16 g_Xlo[(size_t)MROWS * DD];
__device__ __nv_bfloat16 g_Athi[DD * DD];   // A^T: [n][k], k contiguous
__device__ __nv_bfloat16 g_Atlo[DD * DD];

// ---------------------------------------------------------------------------
__device__ __forceinline__ uint32_t smem_u32(const void* p) {
    uint32_t a;
    asm("{ .reg .u64 t; cvta.to.shared.u64 t, %1; cvt.u32.u64 %0, t; }" : "=r"(a) : "l"(p));
    return a;
}
__device__ __forceinline__ void ldsm_x4(uint32_t* r, uint32_t addr) {
    asm volatile("ldmatrix.sync.aligned.m8n8.x4.shared.b16 {%0,%1,%2,%3}, [%4];"
                 : "=r"(r[0]), "=r"(r[1]), "=r"(r[2]), "=r"(r[3]) : "r"(addr));
}
__device__ __forceinline__ void mma_bf16(float* c, const uint32_t* a, const uint32_t* b) {
    asm volatile("mma.sync.aligned.m16n8k16.row.col.f32.bf16.bf16.f32 "
                 "{%0,%1,%2,%3}, {%4,%5,%6,%7}, {%8,%9}, {%0,%1,%2,%3};"
                 : "+f"(c[0]), "+f"(c[1]), "+f"(c[2]), "+f"(c[3])
                 : "r"(a[0]), "r"(a[1]), "r"(a[2]), "r"(a[3]), "r"(b[0]), "r"(b[1]));
}
#define CP16(dst, src) \
    asm volatile("cp.async.cg.shared.global [%0], [%1], 16;" :: "r"(dst), "l"(src))
#define CP_COMMIT() asm volatile("cp.async.commit_group;" ::: "memory")
#define CP_WAIT1()  asm volatile("cp.async.wait_group 1;" ::: "memory")

// ---------------------------------------------------------------------------
// Prologue chain (fp32): W^T, Kron stages, splits
// ---------------------------------------------------------------------------
__global__ void transpose_kernel(const float* __restrict__ W, float* __restrict__ Wt) {
    __shared__ float tile[32][33];
    const int j0 = blockIdx.x * 32, o0 = blockIdx.y * 32;
    const int tx = threadIdx.x, ty = threadIdx.y;
#pragma unroll
    for (int r = 0; r < 32; r += 8)
        tile[ty + r][tx] = W[(o0 + ty + r) * DD + (j0 + tx)];
    __syncthreads();
#pragma unroll
    for (int r = 0; r < 32; r += 8)
        Wt[(j0 + ty + r) * DD + (o0 + tx)] = tile[tx][ty + r];
}
__global__ void stage3_kernel(const float* __restrict__ src, float* __restrict__ dst,
                              const float* __restrict__ k3) {
    const int o = blockIdx.x * 256 + threadIdx.x;
    const int i = blockIdx.y;
    const int g = i / 40, a3 = i % 40;
    __shared__ float krow[40];
    if (threadIdx.x < 40) krow[threadIdx.x] = k3[a3 * 40 + threadIdx.x];
    __syncthreads();
    const float* s = src + (g * 40) * DD + o;
    float acc = 0.f;
#pragma unroll 8
    for (int b3 = 0; b3 < 40; b3++) acc += krow[b3] * s[b3 * DD];
    dst[i * DD + o] = acc;
}
__global__ void stage2_kernel(const float* __restrict__ src, float* __restrict__ dst,
                              const float* __restrict__ k2) {
    const int o = blockIdx.x * 256 + threadIdx.x;
    const int i = blockIdx.y;
    const int b1 = i / 320, a2 = (i / 40) % 8, a3 = i % 40;
    const float* s = src + ((b1 * 8) * 40 + a3) * DD + o;
    float acc = 0.f;
#pragma unroll
    for (int b2 = 0; b2 < 8; b2++) acc += __ldg(&k2[a2 * 8 + b2]) * s[b2 * 40 * DD];
    dst[i * DD + o] = acc;
}
__global__ void stage1_kernel(const float* __restrict__ src, float* __restrict__ dst,
                              const float* __restrict__ k1) {
    const int o = blockIdx.x * 256 + threadIdx.x;
    const int i = blockIdx.y;
    const int a1 = i / 320, rem = i % 320;
    const float* s = src + rem * DD + o;
    float acc = 0.f;
#pragma unroll
    for (int b1 = 0; b1 < 4; b1++) acc += __ldg(&k1[a1 * 4 + b1]) * s[b1 * 320 * DD];
    dst[i * DD + o] = acc;
}
__global__ void split_x_kernel(const float* __restrict__ x,
                               __nv_bfloat16* __restrict__ xhi,
                               __nv_bfloat16* __restrict__ xlo) {
    const size_t i4 = ((size_t)blockIdx.x * 256 + threadIdx.x) * 4;
    float4 v = *reinterpret_cast<const float4*>(x + i4);
    float vv[4] = {v.x, v.y, v.z, v.w};
    unsigned short h[4], l[4];
#pragma unroll
    for (int j = 0; j < 4; j++) {
        __nv_bfloat16 hb = __float2bfloat16_rn(vv[j]);
        float r = vv[j] - __bfloat162float(hb);
        h[j] = __bfloat16_as_ushort(hb);
        l[j] = __bfloat16_as_ushort(__float2bfloat16_rn(r));
    }
    uint2 hv, lv;
    hv.x = (uint32_t)h[0] | ((uint32_t)h[1] << 16);
    hv.y = (uint32_t)h[2] | ((uint32_t)h[3] << 16);
    lv.x = (uint32_t)l[0] | ((uint32_t)l[1] << 16);
    lv.y = (uint32_t)l[2] | ((uint32_t)l[3] << 16);
    *reinterpret_cast<uint2*>(xhi + i4) = hv;
    *reinterpret_cast<uint2*>(xlo + i4) = lv;
}
__global__ void split_at_kernel(const float* __restrict__ A,
                                __nv_bfloat16* __restrict__ athi,
                                __nv_bfloat16* __restrict__ atlo) {
    __shared__ float t[32][33];
    const int k0 = blockIdx.x * 32, n0 = blockIdx.y * 32;
    const int tx = threadIdx.x, ty = threadIdx.y;
#pragma unroll
    for (int r = 0; r < 32; r += 8)
        t[ty + r][tx] = A[(k0 + ty + r) * DD + (n0 + tx)];
    __syncthreads();
#pragma unroll
    for (int r = 0; r < 32; r += 8) {
        float v = t[tx][ty + r];
        __nv_bfloat16 hb = __float2bfloat16_rn(v);
        float rr = v - __bfloat162float(hb);
        athi[(n0 + ty + r) * DD + (k0 + tx)] = hb;
        atlo[(n0 + ty + r) * DD + (k0 + tx)] = __float2bfloat16_rn(rr);
    }
}

// ---------------------------------------------------------------------------
// HMMA split-bf16 GEMM. CTA tile 128x128, BK=32, 256 threads, NSTAGE=2,
// 2 CTAs/SM. smem rows padded to 40 bf16 (80 B) -> conflict-free ldmatrix.
// ---------------------------------------------------------------------------
#define BK 32
#define PADK 40
#define XTB (128 * PADK * 2)        // 10240 B per tile
#define STB (4 * XTB)               // stage: Xhi, Xlo, Ahi, Alo = 40960 B
#define NSTAGE 2
#define GEMM_SMEM (NSTAGE * STB)    // 81920 B
#define KTILES (DD / BK)            // 40

__device__ __forceinline__ void load_stage_async(
    uint32_t sdst,
    const __nv_bfloat16* __restrict__ Xhi, const __nv_bfloat16* __restrict__ Xlo,
    const __nv_bfloat16* __restrict__ Ahi, const __nv_bfloat16* __restrict__ Alo,
    int bm, int bn, int kt, int tid) {
    const int kofs = kt * BK;
#pragma unroll
    for (int i = 0; i < 2; i++) {
        int idx = i * 256 + tid;          // 0..511
        int row = idx >> 2, c = idx & 3;  // 4 x 16B chunks per 64B row
        uint32_t so = (uint32_t)(row * (PADK * 2) + c * 16);
        size_t gx = (size_t)(bm * 128 + row) * DD + kofs + c * 8;
        size_t ga = (size_t)(bn * 128 + row) * DD + kofs + c * 8;
        CP16(sdst + so,           Xhi + gx);
        CP16(sdst + XTB + so,     Xlo + gx);
        CP16(sdst + 2 * XTB + so, Ahi + ga);
        CP16(sdst + 3 * XTB + so, Alo + ga);
    }
}

__global__ __launch_bounds__(256, 2)
void gemm_hmma_kernel(const __nv_bfloat16* __restrict__ Xhi,
                      const __nv_bfloat16* __restrict__ Xlo,
                      const __nv_bfloat16* __restrict__ Athi,
                      const __nv_bfloat16* __restrict__ Atlo,
                      float* __restrict__ out) {
    extern __shared__ __align__(128) char smem[];
    const uint32_t sbase = smem_u32(smem);
    const int tid = threadIdx.x, lane = tid & 31, wid = tid >> 5;
    const int warp_m = wid & 3, warp_n = wid >> 2;   // 4 x 2 warps, tile 32x64
    const int bn = blockIdx.x, bm = blockIdx.y;

    float acc[2][8][4];
#pragma unroll
    for (int a = 0; a < 2; a++)
#pragma unroll
        for (int b = 0; b < 8; b++)
#pragma unroll
            for (int c = 0; c < 4; c++) acc[a][b][c] = 0.f;

    load_stage_async(sbase, Xhi, Xlo, Athi, Atlo, bm, bn, 0, tid);
    CP_COMMIT();
    load_stage_async(sbase + STB, Xhi, Xlo, Athi, Atlo, bm, bn, 1, tid);
    CP_COMMIT();

    // per-thread ldmatrix lane addressing (byte offsets within a tile)
    const uint32_t a_row = (uint32_t)(warp_m * 32 + (lane & 7) + ((lane >> 3) & 1) * 8);
    const uint32_t a_colb = (uint32_t)(((lane >> 4) & 1) * 8) * 2;
    const uint32_t b_nrow = (uint32_t)(warp_n * 64 + (lane & 7) + ((lane >> 4) & 1) * 8);
    const uint32_t b_kb = (uint32_t)(((lane >> 3) & 1) * 8) * 2;

    for (int kt = 0; kt < KTILES; kt++) {
        CP_WAIT1();
        __syncthreads();
        const uint32_t st = sbase + (uint32_t)(kt & 1) * STB;
        const uint32_t sXh = st, sXl = st + XTB, sAh = st + 2 * XTB, sAl = st + 3 * XTB;
#pragma unroll
        for (int kk = 0; kk < 2; kk++) {
            const uint32_t acol = a_colb + kk * 32;   // kk*16 elems * 2B
            const uint32_t bcol = b_kb + kk * 32;
            uint32_t ah[2][4], al[2][4];
            ldsm_x4(ah[0], sXh + a_row * (PADK * 2) + acol);
            ldsm_x4(ah[1], sXh + (a_row + 16) * (PADK * 2) + acol);
            ldsm_x4(al[0], sXl + a_row * (PADK * 2) + acol);
            ldsm_x4(al[1], sXl + (a_row + 16) * (PADK * 2) + acol);
            // B in two 32-column halves to cap live registers (2 CTA/SM).
#pragma unroll
            for (int half = 0; half < 2; half++) {
                uint32_t bh[4][2], bl[4][2];
#pragma unroll
                for (int j = 0; j < 2; j++) {
                    uint32_t r[4];
                    ldsm_x4(r, sAh + (b_nrow + (half * 2 + j) * 16) * (PADK * 2) + bcol);
                    bh[2 * j][0] = r[0]; bh[2 * j][1] = r[1];
                    bh[2 * j + 1][0] = r[2]; bh[2 * j + 1][1] = r[3];
                    ldsm_x4(r, sAl + (b_nrow + (half * 2 + j) * 16) * (PADK * 2) + bcol);
                    bl[2 * j][0] = r[0]; bl[2 * j][1] = r[1];
                    bl[2 * j + 1][0] = r[2]; bl[2 * j + 1][1] = r[3];
                }
#pragma unroll
                for (int mi = 0; mi < 2; mi++)
#pragma unroll
                    for (int nj = 0; nj < 4; nj++) {
                        float* c = acc[mi][half * 4 + nj];
                        mma_bf16(c, ah[mi], bh[nj]);
                        mma_bf16(c, ah[mi], bl[nj]);
                        mma_bf16(c, al[mi], bh[nj]);
                    }
            }
        }
        __syncthreads();
        if (kt + 2 < KTILES)
            load_stage_async(sbase + (uint32_t)(kt & 1) * STB,
                             Xhi, Xlo, Athi, Atlo, bm, bn, kt + 2, tid);
        CP_COMMIT();   // unconditional: keeps wait_group(1) draining the right group
    }

    // epilogue
    const int er = lane >> 2, ec = (lane & 3) * 2;
#pragma unroll
    for (int mi = 0; mi < 2; mi++) {
        const int row = bm * 128 + warp_m * 32 + mi * 16 + er;
#pragma unroll
        for (int nt = 0; nt < 8; nt++) {
            const int col = bn * 128 + warp_n * 64 + nt * 8 + ec;
            *reinterpret_cast<float2*>(out + (size_t)row * DD + col) =
                make_float2(acc[mi][nt][0], acc[mi][nt][1]);
            *reinterpret_cast<float2*>(out + (size_t)(row + 8) * DD + col) =
                make_float2(acc[mi][nt][2], acc[mi][nt][3]);
        }
    }
}

// ---------------------------------------------------------------------------
extern "C" void kernel_launch(void* const* d_in, const int* in_sizes, int n_in,
                              void* d_out, int out_size) {
    const float* x  = (const float*)d_in[0];
    const float* W  = (const float*)d_in[1];
    const float* k1 = (const float*)d_in[2];
    const float* k2 = (const float*)d_in[3];
    const float* k3 = (const float*)d_in[4];
    float* out = (float*)d_out;

    float *buf0, *buf1;
    __nv_bfloat16 *xhi, *xlo, *athi, *atlo;
    cudaGetSymbolAddress((void**)&buf0, g_buf0);
    cudaGetSymbolAddress((void**)&buf1, g_buf1);
    cudaGetSymbolAddress((void**)&xhi, g_Xhi);
    cudaGetSymbolAddress((void**)&xlo, g_Xlo);
    cudaGetSymbolAddress((void**)&athi, g_Athi);
    cudaGetSymbolAddress((void**)&atlo, g_Atlo);

    {
        size_t n4 = (size_t)MROWS * DD / 4;
        split_x_kernel<<<(unsigned)(n4 / 256), 256>>>(x, xhi, xlo);
    }
    {
        dim3 grid(DD / 32, DD / 32), block(32, 8);
        transpose_kernel<<<grid, block>>>(W, buf0);
    }
    {
        dim3 grid(DD / 256, DD), block(256);
        stage3_kernel<<<grid, block>>>(buf0, buf1, k3);
        stage2_kernel<<<grid, block>>>(buf1, buf0, k2);
        stage1_kernel<<<grid, block>>>(buf0, buf1, k1);
    }
    {
        dim3 grid(DD / 32, DD / 32), block(32, 8);
        split_at_kernel<<<grid, block>>>(buf1, athi, atlo);
    }
    {
        static bool attr_set = false;
        if (!attr_set) {
            cudaFuncSetAttribute(gemm_hmma_kernel,
                                 cudaFuncAttributeMaxDynamicSharedMemorySize, GEMM_SMEM);
            attr_set = true;
        }
        dim3 grid(DD / 128, MROWS / 128);   // (10, 128)
        gemm_hmma_kernel<<<grid, 256, GEMM_SMEM>>>(xhi, xlo, athi, atlo, out);
    }
}

// round 6
// speedup vs baseline: 2.5895x; 1.0041x over previous
#include <cuda_runtime.h>
#include <cuda_bf16.h>
#include <cstdint>

// out[16384,1280] = x[16384,1280] @ A[1280,1280],  A = (k1 (x) k2 (x) k3) @ W^T
// Kron factorization in fp32, then split-precision bf16 HMMA GEMM:
//   D = Xhi*Ahi + Xhi*Alo + Xlo*Ahi   (fp32 accumulate, XloAlo term ~2^-18 dropped)
// R5: inner-loop reorder — 3 products in separate passes so same-accumulator
// HMMA reuse distance is 8 instead of 1 (breaks dependency chains).

#define DD 1280
#define MROWS 16384

__device__ float g_buf0[DD * DD];
__device__ float g_buf1[DD * DD];
__device__ __nv_bfloat16 g_Xhi[(size_t)MROWS * DD];
__device__ __nv_bfloat16 g_Xlo[(size_t)MROWS * DD];
__device__ __nv_bfloat16 g_Athi[DD * DD];   // A^T: [n][k], k contiguous
__device__ __nv_bfloat16 g_Atlo[DD * DD];

// ---------------------------------------------------------------------------
__device__ __forceinline__ uint32_t smem_u32(const void* p) {
    uint32_t a;
    asm("{ .reg .u64 t; cvta.to.shared.u64 t, %1; cvt.u32.u64 %0, t; }" : "=r"(a) : "l"(p));
    return a;
}
__device__ __forceinline__ void ldsm_x4(uint32_t* r, uint32_t addr) {
    asm volatile("ldmatrix.sync.aligned.m8n8.x4.shared.b16 {%0,%1,%2,%3}, [%4];"
                 : "=r"(r[0]), "=r"(r[1]), "=r"(r[2]), "=r"(r[3]) : "r"(addr));
}
__device__ __forceinline__ void mma_bf16(float* c, const uint32_t* a, const uint32_t* b) {
    asm volatile("mma.sync.aligned.m16n8k16.row.col.f32.bf16.bf16.f32 "
                 "{%0,%1,%2,%3}, {%4,%5,%6,%7}, {%8,%9}, {%0,%1,%2,%3};"
                 : "+f"(c[0]), "+f"(c[1]), "+f"(c[2]), "+f"(c[3])
                 : "r"(a[0]), "r"(a[1]), "r"(a[2]), "r"(a[3]), "r"(b[0]), "r"(b[1]));
}
#define CP16(dst, src) \
    asm volatile("cp.async.cg.shared.global [%0], [%1], 16;" :: "r"(dst), "l"(src))
#define CP_COMMIT() asm volatile("cp.async.commit_group;" ::: "memory")
#define CP_WAIT1()  asm volatile("cp.async.wait_group 1;" ::: "memory")

// ---------------------------------------------------------------------------
// Prologue chain (fp32): W^T, Kron stages, splits
// ---------------------------------------------------------------------------
__global__ void transpose_kernel(const float* __restrict__ W, float* __restrict__ Wt) {
    __shared__ float tile[32][33];
    const int j0 = blockIdx.x * 32, o0 = blockIdx.y * 32;
    const int tx = threadIdx.x, ty = threadIdx.y;
#pragma unroll
    for (int r = 0; r < 32; r += 8)
        tile[ty + r][tx] = W[(o0 + ty + r) * DD + (j0 + tx)];
    __syncthreads();
#pragma unroll
    for (int r = 0; r < 32; r += 8)
        Wt[(j0 + ty + r) * DD + (o0 + tx)] = tile[tx][ty + r];
}
__global__ void stage3_kernel(const float* __restrict__ src, float* __restrict__ dst,
                              const float* __restrict__ k3) {
    const int o = blockIdx.x * 256 + threadIdx.x;
    const int i = blockIdx.y;
    const int g = i / 40, a3 = i % 40;
    __shared__ float krow[40];
    if (threadIdx.x < 40) krow[threadIdx.x] = k3[a3 * 40 + threadIdx.x];
    __syncthreads();
    const float* s = src + (g * 40) * DD + o;
    float acc = 0.f;
#pragma unroll 8
    for (int b3 = 0; b3 < 40; b3++) acc += krow[b3] * s[b3 * DD];
    dst[i * DD + o] = acc;
}
__global__ void stage2_kernel(const float* __restrict__ src, float* __restrict__ dst,
                              const float* __restrict__ k2) {
    const int o = blockIdx.x * 256 + threadIdx.x;
    const int i = blockIdx.y;
    const int b1 = i / 320, a2 = (i / 40) % 8, a3 = i % 40;
    const float* s = src + ((b1 * 8) * 40 + a3) * DD + o;
    float acc = 0.f;
#pragma unroll
    for (int b2 = 0; b2 < 8; b2++) acc += __ldg(&k2[a2 * 8 + b2]) * s[b2 * 40 * DD];
    dst[i * DD + o] = acc;
}
__global__ void stage1_kernel(const float* __restrict__ src, float* __restrict__ dst,
                              const float* __restrict__ k1) {
    const int o = blockIdx.x * 256 + threadIdx.x;
    const int i = blockIdx.y;
    const int a1 = i / 320, rem = i % 320;
    const float* s = src + rem * DD + o;
    float acc = 0.f;
#pragma unroll
    for (int b1 = 0; b1 < 4; b1++) acc += __ldg(&k1[a1 * 4 + b1]) * s[b1 * 320 * DD];
    dst[i * DD + o] = acc;
}
__global__ void split_x_kernel(const float* __restrict__ x,
                               __nv_bfloat16* __restrict__ xhi,
                               __nv_bfloat16* __restrict__ xlo) {
    const size_t i4 = ((size_t)blockIdx.x * 256 + threadIdx.x) * 4;
    float4 v = *reinterpret_cast<const float4*>(x + i4);
    float vv[4] = {v.x, v.y, v.z, v.w};
    unsigned short h[4], l[4];
#pragma unroll
    for (int j = 0; j < 4; j++) {
        __nv_bfloat16 hb = __float2bfloat16_rn(vv[j]);
        float r = vv[j] - __bfloat162float(hb);
        h[j] = __bfloat16_as_ushort(hb);
        l[j] = __bfloat16_as_ushort(__float2bfloat16_rn(r));
    }
    uint2 hv, lv;
    hv.x = (uint32_t)h[0] | ((uint32_t)h[1] << 16);
    hv.y = (uint32_t)h[2] | ((uint32_t)h[3] << 16);
    lv.x = (uint32_t)l[0] | ((uint32_t)l[1] << 16);
    lv.y = (uint32_t)l[2] | ((uint32_t)l[3] << 16);
    *reinterpret_cast<uint2*>(xhi + i4) = hv;
    *reinterpret_cast<uint2*>(xlo + i4) = lv;
}
__global__ void split_at_kernel(const float* __restrict__ A,
                                __nv_bfloat16* __restrict__ athi,
                                __nv_bfloat16* __restrict__ atlo) {
    __shared__ float t[32][33];
    const int k0 = blockIdx.x * 32, n0 = blockIdx.y * 32;
    const int tx = threadIdx.x, ty = threadIdx.y;
#pragma unroll
    for (int r = 0; r < 32; r += 8)
        t[ty + r][tx] = A[(k0 + ty + r) * DD + (n0 + tx)];
    __syncthreads();
#pragma unroll
    for (int r = 0; r < 32; r += 8) {
        float v = t[tx][ty + r];
        __nv_bfloat16 hb = __float2bfloat16_rn(v);
        float rr = v - __bfloat162float(hb);
        athi[(n0 + ty + r) * DD + (k0 + tx)] = hb;
        atlo[(n0 + ty + r) * DD + (k0 + tx)] = __float2bfloat16_rn(rr);
    }
}

// ---------------------------------------------------------------------------
// HMMA split-bf16 GEMM. CTA tile 128x128, BK=32, 256 threads, NSTAGE=2,
// 2 CTAs/SM. smem rows padded to 40 bf16 (80 B) -> conflict-free ldmatrix.
// ---------------------------------------------------------------------------
#define BK 32
#define PADK 40
#define XTB (128 * PADK * 2)        // 10240 B per tile
#define STB (4 * XTB)               // stage: Xhi, Xlo, Ahi, Alo = 40960 B
#define NSTAGE 2
#define GEMM_SMEM (NSTAGE * STB)    // 81920 B
#define KTILES (DD / BK)            // 40

__device__ __forceinline__ void load_stage_async(
    uint32_t sdst,
    const __nv_bfloat16* __restrict__ Xhi, const __nv_bfloat16* __restrict__ Xlo,
    const __nv_bfloat16* __restrict__ Ahi, const __nv_bfloat16* __restrict__ Alo,
    int bm, int bn, int kt, int tid) {
    const int kofs = kt * BK;
#pragma unroll
    for (int i = 0; i < 2; i++) {
        int idx = i * 256 + tid;          // 0..511
        int row = idx >> 2, c = idx & 3;  // 4 x 16B chunks per 64B row
        uint32_t so = (uint32_t)(row * (PADK * 2) + c * 16);
        size_t gx = (size_t)(bm * 128 + row) * DD + kofs + c * 8;
        size_t ga = (size_t)(bn * 128 + row) * DD + kofs + c * 8;
        CP16(sdst + so,           Xhi + gx);
        CP16(sdst + XTB + so,     Xlo + gx);
        CP16(sdst + 2 * XTB + so, Ahi + ga);
        CP16(sdst + 3 * XTB + so, Alo + ga);
    }
}

__global__ __launch_bounds__(256, 2)
void gemm_hmma_kernel(const __nv_bfloat16* __restrict__ Xhi,
                      const __nv_bfloat16* __restrict__ Xlo,
                      const __nv_bfloat16* __restrict__ Athi,
                      const __nv_bfloat16* __restrict__ Atlo,
                      float* __restrict__ out) {
    extern __shared__ __align__(128) char smem[];
    const uint32_t sbase = smem_u32(smem);
    const int tid = threadIdx.x, lane = tid & 31, wid = tid >> 5;
    const int warp_m = wid & 3, warp_n = wid >> 2;   // 4 x 2 warps, tile 32x64
    const int bn = blockIdx.x, bm = blockIdx.y;

    float acc[2][8][4];
#pragma unroll
    for (int a = 0; a < 2; a++)
#pragma unroll
        for (int b = 0; b < 8; b++)
#pragma unroll
            for (int c = 0; c < 4; c++) acc[a][b][c] = 0.f;

    load_stage_async(sbase, Xhi, Xlo, Athi, Atlo, bm, bn, 0, tid);
    CP_COMMIT();
    load_stage_async(sbase + STB, Xhi, Xlo, Athi, Atlo, bm, bn, 1, tid);
    CP_COMMIT();

    // per-thread ldmatrix lane addressing (byte offsets within a tile)
    const uint32_t a_row = (uint32_t)(warp_m * 32 + (lane & 7) + ((lane >> 3) & 1) * 8);
    const uint32_t a_colb = (uint32_t)(((lane >> 4) & 1) * 8) * 2;
    const uint32_t b_nrow = (uint32_t)(warp_n * 64 + (lane & 7) + ((lane >> 4) & 1) * 8);
    const uint32_t b_kb = (uint32_t)(((lane >> 3) & 1) * 8) * 2;

    for (int kt = 0; kt < KTILES; kt++) {
        CP_WAIT1();
        __syncthreads();
        const uint32_t st = sbase + (uint32_t)(kt & 1) * STB;
        const uint32_t sXh = st, sXl = st + XTB, sAh = st + 2 * XTB, sAl = st + 3 * XTB;
#pragma unroll
        for (int kk = 0; kk < 2; kk++) {
            const uint32_t acol = a_colb + kk * 32;   // kk*16 elems * 2B
            const uint32_t bcol = b_kb + kk * 32;
            uint32_t ah[2][4], al[2][4];
            ldsm_x4(ah[0], sXh + a_row * (PADK * 2) + acol);
            ldsm_x4(ah[1], sXh + (a_row + 16) * (PADK * 2) + acol);
            ldsm_x4(al[0], sXl + a_row * (PADK * 2) + acol);
            ldsm_x4(al[1], sXl + (a_row + 16) * (PADK * 2) + acol);
            // B in two 32-column halves to cap live registers (2 CTA/SM).
#pragma unroll
            for (int half = 0; half < 2; half++) {
                uint32_t bh[4][2], bl[4][2];
#pragma unroll
                for (int j = 0; j < 2; j++) {
                    uint32_t r[4];
                    ldsm_x4(r, sAh + (b_nrow + (half * 2 + j) * 16) * (PADK * 2) + bcol);
                    bh[2 * j][0] = r[0]; bh[2 * j][1] = r[1];
                    bh[2 * j + 1][0] = r[2]; bh[2 * j + 1][1] = r[3];
                    ldsm_x4(r, sAl + (b_nrow + (half * 2 + j) * 16) * (PADK * 2) + bcol);
                    bl[2 * j][0] = r[0]; bl[2 * j][1] = r[1];
                    bl[2 * j + 1][0] = r[2]; bl[2 * j + 1][1] = r[3];
                }
                // Pass 1: hi*hi over all 8 accumulators (independent)
#pragma unroll
                for (int mi = 0; mi < 2; mi++)
#pragma unroll
                    for (int nj = 0; nj < 4; nj++)
                        mma_bf16(acc[mi][half * 4 + nj], ah[mi], bh[nj]);
                // Pass 2: hi*lo
#pragma unroll
                for (int mi = 0; mi < 2; mi++)
#pragma unroll
                    for (int nj = 0; nj < 4; nj++)
                        mma_bf16(acc[mi][half * 4 + nj], ah[mi], bl[nj]);
                // Pass 3: lo*hi
#pragma unroll
                for (int mi = 0; mi < 2; mi++)
#pragma unroll
                    for (int nj = 0; nj < 4; nj++)
                        mma_bf16(acc[mi][half * 4 + nj], al[mi], bh[nj]);
            }
        }
        __syncthreads();
        if (kt + 2 < KTILES)
            load_stage_async(sbase + (uint32_t)(kt & 1) * STB,
                             Xhi, Xlo, Athi, Atlo, bm, bn, kt + 2, tid);
        CP_COMMIT();   // unconditional: keeps wait_group(1) draining the right group
    }

    // epilogue
    const int er = lane >> 2, ec = (lane & 3) * 2;
#pragma unroll
    for (int mi = 0; mi < 2; mi++) {
        const int row = bm * 128 + warp_m * 32 + mi * 16 + er;
#pragma unroll
        for (int nt = 0; nt < 8; nt++) {
            const int col = bn * 128 + warp_n * 64 + nt * 8 + ec;
            *reinterpret_cast<float2*>(out + (size_t)row * DD + col) =
                make_float2(acc[mi][nt][0], acc[mi][nt][1]);
            *reinterpret_cast<float2*>(out + (size_t)(row + 8) * DD + col) =
                make_float2(acc[mi][nt][2], acc[mi][nt][3]);
        }
    }
}

// ---------------------------------------------------------------------------
extern "C" void kernel_launch(void* const* d_in, const int* in_sizes, int n_in,
                              void* d_out, int out_size) {
    const float* x  = (const float*)d_in[0];
    const float* W  = (const float*)d_in[1];
    const float* k1 = (const float*)d_in[2];
    const float* k2 = (const float*)d_in[3];
    const float* k3 = (const float*)d_in[4];
    float* out = (float*)d_out;

    float *buf0, *buf1;
    __nv_bfloat16 *xhi, *xlo, *athi, *atlo;
    cudaGetSymbolAddress((void**)&buf0, g_buf0);
    cudaGetSymbolAddress((void**)&buf1, g_buf1);
    cudaGetSymbolAddress((void**)&xhi, g_Xhi);
    cudaGetSymbolAddress((void**)&xlo, g_Xlo);
    cudaGetSymbolAddress((void**)&athi, g_Athi);
    cudaGetSymbolAddress((void**)&atlo, g_Atlo);

    {
        size_t n4 = (size_t)MROWS * DD / 4;
        split_x_kernel<<<(unsigned)(n4 / 256), 256>>>(x, xhi, xlo);
    }
    {
        dim3 grid(DD / 32, DD / 32), block(32, 8);
        transpose_kernel<<<grid, block>>>(W, buf0);
    }
    {
        dim3 grid(DD / 256, DD), block(256);
        stage3_kernel<<<grid, block>>>(buf0, buf1, k3);
        stage2_kernel<<<grid, block>>>(buf1, buf0, k2);
        stage1_kernel<<<grid, block>>>(buf0, buf1, k1);
    }
    {
        dim3 grid(DD / 32, DD / 32), block(32, 8);
        split_at_kernel<<<grid, block>>>(buf1, athi, atlo);
    }
    {
        static bool attr_set = false;
        if (!attr_set) {
            cudaFuncSetAttribute(gemm_hmma_kernel,
                                 cudaFuncAttributeMaxDynamicSharedMemorySize, GEMM_SMEM);
            attr_set = true;
        }
        dim3 grid(DD / 128, MROWS / 128);   // (10, 128)
        gemm_hmma_kernel<<<grid, 256, GEMM_SMEM>>>(xhi, xlo, athi, atlo, out);
    }
}

// round 7
// speedup vs baseline: 3.3219x; 1.2828x over previous
#include <cuda_runtime.h>
#include <cuda_fp16.h>
#include <cuda_bf16.h>
#include <cstdint>

// out[16384,1280] = x[16384,1280] @ A[1280,1280],  A = (k1 (x) k2 (x) k3) @ W^T
// Kron factorization in fp32, then fp16 2-product HMMA GEMM:
//   A*64 = Ahi + Alo (fp16 pair, exact to ~2^-22), x ~= Xh (fp16, err 2^-12)
//   D = (Xh*Ahi + Xh*Alo) / 64     (fp32 accumulate; dropped Xlo*A ~ 2^-12)
// R6: 2 products instead of 3 (legacy HMMA path is throughput-walled, so cut
// instruction count), X traffic halved, NSTAGE=3 @ 2 CTAs/SM.

#define DD 1280
#define MROWS 16384
#define ASCALE 64.0f
#define INV_ASCALE (1.0f / 64.0f)

__device__ float g_buf0[DD * DD];
__device__ float g_buf1[DD * DD];
__device__ __half g_Xh[(size_t)MROWS * DD];
__device__ __half g_Athi[DD * DD];   // (A^T)*64 hi: [n][k], k contiguous
__device__ __half g_Atlo[DD * DD];   // (A^T)*64 lo

// ---------------------------------------------------------------------------
__device__ __forceinline__ uint32_t smem_u32(const void* p) {
    uint32_t a;
    asm("{ .reg .u64 t; cvta.to.shared.u64 t, %1; cvt.u32.u64 %0, t; }" : "=r"(a) : "l"(p));
    return a;
}
__device__ __forceinline__ void ldsm_x4(uint32_t* r, uint32_t addr) {
    asm volatile("ldmatrix.sync.aligned.m8n8.x4.shared.b16 {%0,%1,%2,%3}, [%4];"
                 : "=r"(r[0]), "=r"(r[1]), "=r"(r[2]), "=r"(r[3]) : "r"(addr));
}
__device__ __forceinline__ void mma_f16(float* c, const uint32_t* a, const uint32_t* b) {
    asm volatile("mma.sync.aligned.m16n8k16.row.col.f32.f16.f16.f32 "
                 "{%0,%1,%2,%3}, {%4,%5,%6,%7}, {%8,%9}, {%0,%1,%2,%3};"
                 : "+f"(c[0]), "+f"(c[1]), "+f"(c[2]), "+f"(c[3])
                 : "r"(a[0]), "r"(a[1]), "r"(a[2]), "r"(a[3]), "r"(b[0]), "r"(b[1]));
}
#define CP16(dst, src) \
    asm volatile("cp.async.cg.shared.global [%0], [%1], 16;" :: "r"(dst), "l"(src))
#define CP_COMMIT() asm volatile("cp.async.commit_group;" ::: "memory")
#define CP_WAIT2()  asm volatile("cp.async.wait_group 2;" ::: "memory")

// ---------------------------------------------------------------------------
// Prologue chain (fp32): W^T, Kron stages, splits
// ---------------------------------------------------------------------------
__global__ void transpose_kernel(const float* __restrict__ W, float* __restrict__ Wt) {
    __shared__ float tile[32][33];
    const int j0 = blockIdx.x * 32, o0 = blockIdx.y * 32;
    const int tx = threadIdx.x, ty = threadIdx.y;
#pragma unroll
    for (int r = 0; r < 32; r += 8)
        tile[ty + r][tx] = W[(o0 + ty + r) * DD + (j0 + tx)];
    __syncthreads();
#pragma unroll
    for (int r = 0; r < 32; r += 8)
        Wt[(j0 + ty + r) * DD + (o0 + tx)] = tile[tx][ty + r];
}
__global__ void stage3_kernel(const float* __restrict__ src, float* __restrict__ dst,
                              const float* __restrict__ k3) {
    const int o = blockIdx.x * 256 + threadIdx.x;
    const int i = blockIdx.y;
    const int g = i / 40, a3 = i % 40;
    __shared__ float krow[40];
    if (threadIdx.x < 40) krow[threadIdx.x] = k3[a3 * 40 + threadIdx.x];
    __syncthreads();
    const float* s = src + (g * 40) * DD + o;
    float acc = 0.f;
#pragma unroll 8
    for (int b3 = 0; b3 < 40; b3++) acc += krow[b3] * s[b3 * DD];
    dst[i * DD + o] = acc;
}
__global__ void stage2_kernel(const float* __restrict__ src, float* __restrict__ dst,
                              const float* __restrict__ k2) {
    const int o = blockIdx.x * 256 + threadIdx.x;
    const int i = blockIdx.y;
    const int b1 = i / 320, a2 = (i / 40) % 8, a3 = i % 40;
    const float* s = src + ((b1 * 8) * 40 + a3) * DD + o;
    float acc = 0.f;
#pragma unroll
    for (int b2 = 0; b2 < 8; b2++) acc += __ldg(&k2[a2 * 8 + b2]) * s[b2 * 40 * DD];
    dst[i * DD + o] = acc;
}
__global__ void stage1_kernel(const float* __restrict__ src, float* __restrict__ dst,
                              const float* __restrict__ k1) {
    const int o = blockIdx.x * 256 + threadIdx.x;
    const int i = blockIdx.y;
    const int a1 = i / 320, rem = i % 320;
    const float* s = src + rem * DD + o;
    float acc = 0.f;
#pragma unroll
    for (int b1 = 0; b1 < 4; b1++) acc += __ldg(&k1[a1 * 4 + b1]) * s[b1 * 320 * DD];
    dst[i * DD + o] = acc;
}
// x -> fp16 (single rounding)
__global__ void cvt_x_kernel(const float* __restrict__ x, __half* __restrict__ xh) {
    const size_t i4 = ((size_t)blockIdx.x * 256 + threadIdx.x) * 4;
    float4 v = *reinterpret_cast<const float4*>(x + i4);
    __half2 a = __floats2half2_rn(v.x, v.y);
    __half2 b = __floats2half2_rn(v.z, v.w);
    *reinterpret_cast<uint2*>(xh + i4) =
        make_uint2(*reinterpret_cast<uint32_t*>(&a), *reinterpret_cast<uint32_t*>(&b));
}
// A[k][n] -> At[n][k] * 64 split into fp16 hi/lo
__global__ void split_at_kernel(const float* __restrict__ A,
                                __half* __restrict__ athi,
                                __half* __restrict__ atlo) {
    __shared__ float t[32][33];
    const int k0 = blockIdx.x * 32, n0 = blockIdx.y * 32;
    const int tx = threadIdx.x, ty = threadIdx.y;
#pragma unroll
    for (int r = 0; r < 32; r += 8)
        t[ty + r][tx] = A[(k0 + ty + r) * DD + (n0 + tx)];
    __syncthreads();
#pragma unroll
    for (int r = 0; r < 32; r += 8) {
        float v = t[tx][ty + r] * ASCALE;
        __half hb = __float2half_rn(v);
        float rr = v - __half2float(hb);
        athi[(n0 + ty + r) * DD + (k0 + tx)] = hb;
        atlo[(n0 + ty + r) * DD + (k0 + tx)] = __float2half_rn(rr);
    }
}

// ---------------------------------------------------------------------------
// HMMA fp16 2-product GEMM. CTA tile 128x128, BK=32, 256 threads, NSTAGE=3,
// 2 CTAs/SM. smem rows padded to 40 halves (80 B) -> conflict-free ldmatrix.
// ---------------------------------------------------------------------------
#define BK 32
#define PADK 40
#define XTB (128 * PADK * 2)        // 10240 B per tile
#define STB (3 * XTB)               // stage: Xh, Ahi, Alo = 30720 B
#define NSTAGE 3
#define GEMM_SMEM (NSTAGE * STB)    // 92160 B
#define KTILES (DD / BK)            // 40

__device__ __forceinline__ void load_stage_async(
    uint32_t sdst,
    const __half* __restrict__ Xh,
    const __half* __restrict__ Ahi, const __half* __restrict__ Alo,
    int bm, int bn, int kt, int tid) {
    const int kofs = kt * BK;
#pragma unroll
    for (int i = 0; i < 2; i++) {
        int idx = i * 256 + tid;          // 0..511
        int row = idx >> 2, c = idx & 3;  // 4 x 16B chunks per 64B data row
        uint32_t so = (uint32_t)(row * (PADK * 2) + c * 16);
        size_t gx = (size_t)(bm * 128 + row) * DD + kofs + c * 8;
        size_t ga = (size_t)(bn * 128 + row) * DD + kofs + c * 8;
        CP16(sdst + so,           Xh  + gx);
        CP16(sdst + XTB + so,     Ahi + ga);
        CP16(sdst + 2 * XTB + so, Alo + ga);
    }
}

__global__ __launch_bounds__(256, 2)
void gemm_hmma_kernel(const __half* __restrict__ Xh,
                      const __half* __restrict__ Athi,
                      const __half* __restrict__ Atlo,
                      float* __restrict__ out) {
    extern __shared__ __align__(128) char smem[];
    const uint32_t sbase = smem_u32(smem);
    const int tid = threadIdx.x, lane = tid & 31, wid = tid >> 5;
    const int warp_m = wid & 3, warp_n = wid >> 2;   // 4 x 2 warps, tile 32x64
    const int bn = blockIdx.x, bm = blockIdx.y;

    float acc[2][8][4];
#pragma unroll
    for (int a = 0; a < 2; a++)
#pragma unroll
        for (int b = 0; b < 8; b++)
#pragma unroll
            for (int c = 0; c < 4; c++) acc[a][b][c] = 0.f;

    load_stage_async(sbase, Xh, Athi, Atlo, bm, bn, 0, tid);
    CP_COMMIT();
    load_stage_async(sbase + STB, Xh, Athi, Atlo, bm, bn, 1, tid);
    CP_COMMIT();
    load_stage_async(sbase + 2 * STB, Xh, Athi, Atlo, bm, bn, 2, tid);
    CP_COMMIT();

    // per-thread ldmatrix lane addressing (byte offsets within a tile)
    const uint32_t a_row = (uint32_t)(warp_m * 32 + (lane & 7) + ((lane >> 3) & 1) * 8);
    const uint32_t a_colb = (uint32_t)(((lane >> 4) & 1) * 8) * 2;
    const uint32_t b_nrow = (uint32_t)(warp_n * 64 + (lane & 7) + ((lane >> 4) & 1) * 8);
    const uint32_t b_kb = (uint32_t)(((lane >> 3) & 1) * 8) * 2;

    for (int kt = 0; kt < KTILES; kt++) {
        CP_WAIT2();
        __syncthreads();
        const uint32_t st = sbase + (uint32_t)(kt % NSTAGE) * STB;
        const uint32_t sX = st, sAh = st + XTB, sAl = st + 2 * XTB;
#pragma unroll
        for (int kk = 0; kk < 2; kk++) {
            const uint32_t acol = a_colb + kk * 32;   // kk*16 elems * 2B
            const uint32_t bcol = b_kb + kk * 32;
            uint32_t ax[2][4];
            ldsm_x4(ax[0], sX + a_row * (PADK * 2) + acol);
            ldsm_x4(ax[1], sX + (a_row + 16) * (PADK * 2) + acol);
            // B in two 32-column halves to cap live registers (2 CTA/SM).
#pragma unroll
            for (int half = 0; half < 2; half++) {
                uint32_t bh[4][2], bl[4][2];
#pragma unroll
                for (int j = 0; j < 2; j++) {
                    uint32_t r[4];
                    ldsm_x4(r, sAh + (b_nrow + (half * 2 + j) * 16) * (PADK * 2) + bcol);
                    bh[2 * j][0] = r[0]; bh[2 * j][1] = r[1];
                    bh[2 * j + 1][0] = r[2]; bh[2 * j + 1][1] = r[3];
                    ldsm_x4(r, sAl + (b_nrow + (half * 2 + j) * 16) * (PADK * 2) + bcol);
                    bl[2 * j][0] = r[0]; bl[2 * j][1] = r[1];
                    bl[2 * j + 1][0] = r[2]; bl[2 * j + 1][1] = r[3];
                }
                // Pass 1: Xh * Ahi
#pragma unroll
                for (int mi = 0; mi < 2; mi++)
#pragma unroll
                    for (int nj = 0; nj < 4; nj++)
                        mma_f16(acc[mi][half * 4 + nj], ax[mi], bh[nj]);
                // Pass 2: Xh * Alo
#pragma unroll
                for (int mi = 0; mi < 2; mi++)
#pragma unroll
                    for (int nj = 0; nj < 4; nj++)
                        mma_f16(acc[mi][half * 4 + nj], ax[mi], bl[nj]);
            }
        }
        __syncthreads();
        if (kt + 3 < KTILES)
            load_stage_async(sbase + (uint32_t)((kt + 3) % NSTAGE) * STB,
                             Xh, Athi, Atlo, bm, bn, kt + 3, tid);
        CP_COMMIT();   // unconditional: keeps wait_group(2) draining the right group
    }

    // epilogue (undo ASCALE)
    const int er = lane >> 2, ec = (lane & 3) * 2;
#pragma unroll
    for (int mi = 0; mi < 2; mi++) {
        const int row = bm * 128 + warp_m * 32 + mi * 16 + er;
#pragma unroll
        for (int nt = 0; nt < 8; nt++) {
            const int col = bn * 128 + warp_n * 64 + nt * 8 + ec;
            *reinterpret_cast<float2*>(out + (size_t)row * DD + col) =
                make_float2(acc[mi][nt][0] * INV_ASCALE, acc[mi][nt][1] * INV_ASCALE);
            *reinterpret_cast<float2*>(out + (size_t)(row + 8) * DD + col) =
                make_float2(acc[mi][nt][2] * INV_ASCALE, acc[mi][nt][3] * INV_ASCALE);
        }
    }
}

// ---------------------------------------------------------------------------
extern "C" void kernel_launch(void* const* d_in, const int* in_sizes, int n_in,
                              void* d_out, int out_size) {
    const float* x  = (const float*)d_in[0];
    const float* W  = (const float*)d_in[1];
    const float* k1 = (const float*)d_in[2];
    const float* k2 = (const float*)d_in[3];
    const float* k3 = (const float*)d_in[4];
    float* out = (float*)d_out;

    float *buf0, *buf1;
    __half *xh, *athi, *atlo;
    cudaGetSymbolAddress((void**)&buf0, g_buf0);
    cudaGetSymbolAddress((void**)&buf1, g_buf1);
    cudaGetSymbolAddress((void**)&xh, g_Xh);
    cudaGetSymbolAddress((void**)&athi, g_Athi);
    cudaGetSymbolAddress((void**)&atlo, g_Atlo);

    {
        size_t n4 = (size_t)MROWS * DD / 4;
        cvt_x_kernel<<<(unsigned)(n4 / 256), 256>>>(x, xh);
    }
    {
        dim3 grid(DD / 32, DD / 32), block(32, 8);
        transpose_kernel<<<grid, block>>>(W, buf0);
    }
    {
        dim3 grid(DD / 256, DD), block(256);
        stage3_kernel<<<grid, block>>>(buf0, buf1, k3);
        stage2_kernel<<<grid, block>>>(buf1, buf0, k2);
        stage1_kernel<<<grid, block>>>(buf0, buf1, k1);
    }
    {
        dim3 grid(DD / 32, DD / 32), block(32, 8);
        split_at_kernel<<<grid, block>>>(buf1, athi, atlo);
    }
    {
        static bool attr_set = false;
        if (!attr_set) {
            cudaFuncSetAttribute(gemm_hmma_kernel,
                                 cudaFuncAttributeMaxDynamicSharedMemorySize, GEMM_SMEM);
            attr_set = true;
        }
        dim3 grid(DD / 128, MROWS / 128);   // (10, 128)
        gemm_hmma_kernel<<<grid, 256, GEMM_SMEM>>>(xh, athi, atlo, out);
    }
}

// round 8
// speedup vs baseline: 5.5044x; 1.6570x over previous
#include <cuda_runtime.h>
#include <cuda_fp16.h>
#include <cstdint>

// out[16384,1280] = x[16384,1280] @ A[1280,1280],  A = (k1 (x) k2 (x) k3) @ W^T
// Kron factorization in fp32, then SINGLE-product fp16 HMMA GEMM:
//   D = fp16(x) * fp16(A^T)   (fp32 accumulate)
// Error model (validated R3/R6): x-round 2^-12 and A-round 2^-12 incoherent
// -> rel_err ~2.9e-4, gate is 1e-3.
// R7: halve HMMA count vs R6; NSTAGE=4, 2 CTAs/SM.

#define DD 1280
#define MROWS 16384

__device__ float g_buf0[DD * DD];
__device__ float g_buf1[DD * DD];
__device__ __half g_Xh[(size_t)MROWS * DD];
__device__ __half g_Ath[DD * DD];   // fp16(A^T): [n][k], k contiguous

// ---------------------------------------------------------------------------
__device__ __forceinline__ uint32_t smem_u32(const void* p) {
    uint32_t a;
    asm("{ .reg .u64 t; cvta.to.shared.u64 t, %1; cvt.u32.u64 %0, t; }" : "=r"(a) : "l"(p));
    return a;
}
__device__ __forceinline__ void ldsm_x4(uint32_t* r, uint32_t addr) {
    asm volatile("ldmatrix.sync.aligned.m8n8.x4.shared.b16 {%0,%1,%2,%3}, [%4];"
                 : "=r"(r[0]), "=r"(r[1]), "=r"(r[2]), "=r"(r[3]) : "r"(addr));
}
__device__ __forceinline__ void mma_f16(float* c, const uint32_t* a, const uint32_t* b) {
    asm volatile("mma.sync.aligned.m16n8k16.row.col.f32.f16.f16.f32 "
                 "{%0,%1,%2,%3}, {%4,%5,%6,%7}, {%8,%9}, {%0,%1,%2,%3};"
                 : "+f"(c[0]), "+f"(c[1]), "+f"(c[2]), "+f"(c[3])
                 : "r"(a[0]), "r"(a[1]), "r"(a[2]), "r"(a[3]), "r"(b[0]), "r"(b[1]));
}
#define CP16(dst, src) \
    asm volatile("cp.async.cg.shared.global [%0], [%1], 16;" :: "r"(dst), "l"(src))
#define CP_COMMIT() asm volatile("cp.async.commit_group;" ::: "memory")
#define CP_WAIT2()  asm volatile("cp.async.wait_group 2;" ::: "memory")

// ---------------------------------------------------------------------------
// Prologue chain (fp32): W^T, Kron stages, converts
// ---------------------------------------------------------------------------
__global__ void transpose_kernel(const float* __restrict__ W, float* __restrict__ Wt) {
    __shared__ float tile[32][33];
    const int j0 = blockIdx.x * 32, o0 = blockIdx.y * 32;
    const int tx = threadIdx.x, ty = threadIdx.y;
#pragma unroll
    for (int r = 0; r < 32; r += 8)
        tile[ty + r][tx] = W[(o0 + ty + r) * DD + (j0 + tx)];
    __syncthreads();
#pragma unroll
    for (int r = 0; r < 32; r += 8)
        Wt[(j0 + ty + r) * DD + (o0 + tx)] = tile[tx][ty + r];
}
__global__ void stage3_kernel(const float* __restrict__ src, float* __restrict__ dst,
                              const float* __restrict__ k3) {
    const int o = blockIdx.x * 256 + threadIdx.x;
    const int i = blockIdx.y;
    const int g = i / 40, a3 = i % 40;
    __shared__ float krow[40];
    if (threadIdx.x < 40) krow[threadIdx.x] = k3[a3 * 40 + threadIdx.x];
    __syncthreads();
    const float* s = src + (g * 40) * DD + o;
    float acc = 0.f;
#pragma unroll 8
    for (int b3 = 0; b3 < 40; b3++) acc += krow[b3] * s[b3 * DD];
    dst[i * DD + o] = acc;
}
__global__ void stage2_kernel(const float* __restrict__ src, float* __restrict__ dst,
                              const float* __restrict__ k2) {
    const int o = blockIdx.x * 256 + threadIdx.x;
    const int i = blockIdx.y;
    const int b1 = i / 320, a2 = (i / 40) % 8, a3 = i % 40;
    const float* s = src + ((b1 * 8) * 40 + a3) * DD + o;
    float acc = 0.f;
#pragma unroll
    for (int b2 = 0; b2 < 8; b2++) acc += __ldg(&k2[a2 * 8 + b2]) * s[b2 * 40 * DD];
    dst[i * DD + o] = acc;
}
__global__ void stage1_kernel(const float* __restrict__ src, float* __restrict__ dst,
                              const float* __restrict__ k1) {
    const int o = blockIdx.x * 256 + threadIdx.x;
    const int i = blockIdx.y;
    const int a1 = i / 320, rem = i % 320;
    const float* s = src + rem * DD + o;
    float acc = 0.f;
#pragma unroll
    for (int b1 = 0; b1 < 4; b1++) acc += __ldg(&k1[a1 * 4 + b1]) * s[b1 * 320 * DD];
    dst[i * DD + o] = acc;
}
// x -> fp16
__global__ void cvt_x_kernel(const float* __restrict__ x, __half* __restrict__ xh) {
    const size_t i4 = ((size_t)blockIdx.x * 256 + threadIdx.x) * 4;
    float4 v = *reinterpret_cast<const float4*>(x + i4);
    __half2 a = __floats2half2_rn(v.x, v.y);
    __half2 b = __floats2half2_rn(v.z, v.w);
    *reinterpret_cast<uint2*>(xh + i4) =
        make_uint2(*reinterpret_cast<uint32_t*>(&a), *reinterpret_cast<uint32_t*>(&b));
}
// A[k][n] -> fp16(At[n][k])
__global__ void cvt_at_kernel(const float* __restrict__ A, __half* __restrict__ ath) {
    __shared__ float t[32][33];
    const int k0 = blockIdx.x * 32, n0 = blockIdx.y * 32;
    const int tx = threadIdx.x, ty = threadIdx.y;
#pragma unroll
    for (int r = 0; r < 32; r += 8)
        t[ty + r][tx] = A[(k0 + ty + r) * DD + (n0 + tx)];
    __syncthreads();
#pragma unroll
    for (int r = 0; r < 32; r += 8)
        ath[(n0 + ty + r) * DD + (k0 + tx)] = __float2half_rn(t[tx][ty + r]);
}

// ---------------------------------------------------------------------------
// Single-product fp16 HMMA GEMM. CTA tile 128x128, BK=32, 256 threads,
// NSTAGE=4, 2 CTAs/SM. smem rows padded to 40 halves (80 B).
// ---------------------------------------------------------------------------
#define BK 32
#define PADK 40
#define XTB (128 * PADK * 2)        // 10240 B per tile
#define STB (2 * XTB)               // stage: Xh, Ath = 20480 B
#define NSTAGE 4
#define GEMM_SMEM (NSTAGE * STB)    // 81920 B
#define KTILES (DD / BK)            // 40

__device__ __forceinline__ void load_stage_async(
    uint32_t sdst,
    const __half* __restrict__ Xh, const __half* __restrict__ Ath,
    int bm, int bn, int kt, int tid) {
    const int kofs = kt * BK;
#pragma unroll
    for (int i = 0; i < 2; i++) {
        int idx = i * 256 + tid;          // 0..511
        int row = idx >> 2, c = idx & 3;  // 4 x 16B chunks per 64B data row
        uint32_t so = (uint32_t)(row * (PADK * 2) + c * 16);
        size_t gx = (size_t)(bm * 128 + row) * DD + kofs + c * 8;
        size_t ga = (size_t)(bn * 128 + row) * DD + kofs + c * 8;
        CP16(sdst + so,       Xh  + gx);
        CP16(sdst + XTB + so, Ath + ga);
    }
}

__global__ __launch_bounds__(256, 2)
void gemm_hmma_kernel(const __half* __restrict__ Xh,
                      const __half* __restrict__ Ath,
                      float* __restrict__ out) {
    extern __shared__ __align__(128) char smem[];
    const uint32_t sbase = smem_u32(smem);
    const int tid = threadIdx.x, lane = tid & 31, wid = tid >> 5;
    const int warp_m = wid & 3, warp_n = wid >> 2;   // 4 x 2 warps, tile 32x64
    const int bn = blockIdx.x, bm = blockIdx.y;

    float acc[2][8][4];
#pragma unroll
    for (int a = 0; a < 2; a++)
#pragma unroll
        for (int b = 0; b < 8; b++)
#pragma unroll
            for (int c = 0; c < 4; c++) acc[a][b][c] = 0.f;

    load_stage_async(sbase, Xh, Ath, bm, bn, 0, tid);
    CP_COMMIT();
    load_stage_async(sbase + STB, Xh, Ath, bm, bn, 1, tid);
    CP_COMMIT();
    load_stage_async(sbase + 2 * STB, Xh, Ath, bm, bn, 2, tid);
    CP_COMMIT();

    // per-thread ldmatrix lane addressing (byte offsets within a tile)
    const uint32_t a_row = (uint32_t)(warp_m * 32 + (lane & 7) + ((lane >> 3) & 1) * 8);
    const uint32_t a_colb = (uint32_t)(((lane >> 4) & 1) * 8) * 2;
    const uint32_t b_nrow = (uint32_t)(warp_n * 64 + (lane & 7) + ((lane >> 4) & 1) * 8);
    const uint32_t b_kb = (uint32_t)(((lane >> 3) & 1) * 8) * 2;

    for (int kt = 0; kt < KTILES; kt++) {
        CP_WAIT2();
        __syncthreads();
        const uint32_t st = sbase + (uint32_t)(kt % NSTAGE) * STB;
        const uint32_t sX = st, sA = st + XTB;
#pragma unroll
        for (int kk = 0; kk < 2; kk++) {
            const uint32_t acol = a_colb + kk * 32;   // kk*16 elems * 2B
            const uint32_t bcol = b_kb + kk * 32;
            uint32_t ax[2][4];
            ldsm_x4(ax[0], sX + a_row * (PADK * 2) + acol);
            ldsm_x4(ax[1], sX + (a_row + 16) * (PADK * 2) + acol);
            uint32_t bb[8][2];
#pragma unroll
            for (int j = 0; j < 4; j++) {
                uint32_t r[4];
                ldsm_x4(r, sA + (b_nrow + j * 16) * (PADK * 2) + bcol);
                bb[2 * j][0] = r[0]; bb[2 * j][1] = r[1];
                bb[2 * j + 1][0] = r[2]; bb[2 * j + 1][1] = r[3];
            }
#pragma unroll
            for (int mi = 0; mi < 2; mi++)
#pragma unroll
                for (int nj = 0; nj < 8; nj++)
                    mma_f16(acc[mi][nj], ax[mi], bb[nj]);
        }
        __syncthreads();
        if (kt + 3 < KTILES)
            load_stage_async(sbase + (uint32_t)((kt + 3) % NSTAGE) * STB,
                             Xh, Ath, bm, bn, kt + 3, tid);
        CP_COMMIT();   // unconditional: keeps wait_group(2) draining correctly
    }

    // epilogue
    const int er = lane >> 2, ec = (lane & 3) * 2;
#pragma unroll
    for (int mi = 0; mi < 2; mi++) {
        const int row = bm * 128 + warp_m * 32 + mi * 16 + er;
#pragma unroll
        for (int nt = 0; nt < 8; nt++) {
            const int col = bn * 128 + warp_n * 64 + nt * 8 + ec;
            *reinterpret_cast<float2*>(out + (size_t)row * DD + col) =
                make_float2(acc[mi][nt][0], acc[mi][nt][1]);
            *reinterpret_cast<float2*>(out + (size_t)(row + 8) * DD + col) =
                make_float2(acc[mi][nt][2], acc[mi][nt][3]);
        }
    }
}

// ---------------------------------------------------------------------------
extern "C" void kernel_launch(void* const* d_in, const int* in_sizes, int n_in,
                              void* d_out, int out_size) {
    const float* x  = (const float*)d_in[0];
    const float* W  = (const float*)d_in[1];
    const float* k1 = (const float*)d_in[2];
    const float* k2 = (const float*)d_in[3];
    const float* k3 = (const float*)d_in[4];
    float* out = (float*)d_out;

    float *buf0, *buf1;
    __half *xh, *ath;
    cudaGetSymbolAddress((void**)&buf0, g_buf0);
    cudaGetSymbolAddress((void**)&buf1, g_buf1);
    cudaGetSymbolAddress((void**)&xh, g_Xh);
    cudaGetSymbolAddress((void**)&ath, g_Ath);

    {
        size_t n4 = (size_t)MROWS * DD / 4;
        cvt_x_kernel<<<(unsigned)(n4 / 256), 256>>>(x, xh);
    }
    {
        dim3 grid(DD / 32, DD / 32), block(32, 8);
        transpose_kernel<<<grid, block>>>(W, buf0);
    }
    {
        dim3 grid(DD / 256, DD), block(256);
        stage3_kernel<<<grid, block>>>(buf0, buf1, k3);
        stage2_kernel<<<grid, block>>>(buf1, buf0, k2);
        stage1_kernel<<<grid, block>>>(buf0, buf1, k1);
    }
    {
        dim3 grid(DD / 32, DD / 32), block(32, 8);
        cvt_at_kernel<<<grid, block>>>(buf1, ath);
    }
    {
        static bool attr_set = false;
        if (!attr_set) {
            cudaFuncSetAttribute(gemm_hmma_kernel,
                                 cudaFuncAttributeMaxDynamicSharedMemorySize, GEMM_SMEM);
            attr_set = true;
        }
        dim3 grid(DD / 128, MROWS / 128);   // (10, 128)
        gemm_hmma_kernel<<<grid, 256, GEMM_SMEM>>>(xh, ath, out);
    }
}

// round 9
// speedup vs baseline: 5.5965x; 1.0167x over previous
#include <cuda_runtime.h>
#include <cuda_fp16.h>
#include <cstdint>

// out[16384,1280] = x[16384,1280] @ A[1280,1280],  A = (k1 (x) k2 (x) k3) @ W^T
// Kron factorization in fp32, then SINGLE-product fp16 HMMA GEMM:
//   D = fp16(x) * fp16(A^T)   (fp32 accumulate)  rel_err ~2.9e-4 (validated)
// R8: stage1+stage2 fused via k12 = k1 (x) k2; MLP-boosted stage kernels;
// GEMM: one barrier per ktile, NSTAGE=5 / wait_group 3.

#define DD 1280
#define MROWS 16384

__device__ float g_buf0[DD * DD];
__device__ float g_buf1[DD * DD];
__device__ float g_k12[32 * 32];
__device__ __half g_Xh[(size_t)MROWS * DD];
__device__ __half g_Ath[DD * DD];   // fp16(A^T): [n][k], k contiguous

// ---------------------------------------------------------------------------
__device__ __forceinline__ uint32_t smem_u32(const void* p) {
    uint32_t a;
    asm("{ .reg .u64 t; cvta.to.shared.u64 t, %1; cvt.u32.u64 %0, t; }" : "=r"(a) : "l"(p));
    return a;
}
__device__ __forceinline__ void ldsm_x4(uint32_t* r, uint32_t addr) {
    asm volatile("ldmatrix.sync.aligned.m8n8.x4.shared.b16 {%0,%1,%2,%3}, [%4];"
                 : "=r"(r[0]), "=r"(r[1]), "=r"(r[2]), "=r"(r[3]) : "r"(addr));
}
__device__ __forceinline__ void mma_f16(float* c, const uint32_t* a, const uint32_t* b) {
    asm volatile("mma.sync.aligned.m16n8k16.row.col.f32.f16.f16.f32 "
                 "{%0,%1,%2,%3}, {%4,%5,%6,%7}, {%8,%9}, {%0,%1,%2,%3};"
                 : "+f"(c[0]), "+f"(c[1]), "+f"(c[2]), "+f"(c[3])
                 : "r"(a[0]), "r"(a[1]), "r"(a[2]), "r"(a[3]), "r"(b[0]), "r"(b[1]));
}
#define CP16(dst, src) \
    asm volatile("cp.async.cg.shared.global [%0], [%1], 16;" :: "r"(dst), "l"(src))
#define CP_COMMIT() asm volatile("cp.async.commit_group;" ::: "memory")
#define CP_WAIT3()  asm volatile("cp.async.wait_group 3;" ::: "memory")

// ---------------------------------------------------------------------------
// Prologue chain (fp32)
// ---------------------------------------------------------------------------
__global__ void transpose_kernel(const float* __restrict__ W, float* __restrict__ Wt) {
    __shared__ float tile[32][33];
    const int j0 = blockIdx.x * 32, o0 = blockIdx.y * 32;
    const int tx = threadIdx.x, ty = threadIdx.y;
#pragma unroll
    for (int r = 0; r < 32; r += 8)
        tile[ty + r][tx] = W[(o0 + ty + r) * DD + (j0 + tx)];
    __syncthreads();
#pragma unroll
    for (int r = 0; r < 32; r += 8)
        Wt[(j0 + ty + r) * DD + (o0 + tx)] = tile[tx][ty + r];
}
// k12 = kron(k1, k2): k12[a1*8+a2][b1*8+b2] = k1[a1][b1]*k2[a2][b2]
__global__ void kron12_kernel(const float* __restrict__ k1, const float* __restrict__ k2,
                              float* __restrict__ k12) {
    const int t = threadIdx.x;              // 0..1023
    const int r = t >> 5, c = t & 31;       // row, col in 32x32
    k12[t] = k1[(r >> 3) * 4 + (c >> 3)] * k2[(r & 7) * 8 + (c & 7)];
}
// Stage 3 (40-term), 2 output cols per thread for MLP
__global__ void stage3_kernel(const float* __restrict__ src, float* __restrict__ dst,
                              const float* __restrict__ k3) {
    const int o = blockIdx.x * 128 + threadIdx.x;   // grid.x = 5 -> o in [0,640)
    const int i = blockIdx.y;
    const int g = i / 40, a3 = i % 40;
    __shared__ float krow[40];
    if (threadIdx.x < 40) krow[threadIdx.x] = k3[a3 * 40 + threadIdx.x];
    __syncthreads();
    const float* s = src + (g * 40) * DD + o;
    float acc0 = 0.f, acc1 = 0.f;
#pragma unroll 8
    for (int b3 = 0; b3 < 40; b3++) {
        float k = krow[b3];
        acc0 += k * s[b3 * DD];
        acc1 += k * s[b3 * DD + 640];
    }
    dst[i * DD + o] = acc0;
    dst[i * DD + o + 640] = acc1;
}
// Fused stage2+stage1 (32-term via k12), 2 output cols per thread
__global__ void stage12_kernel(const float* __restrict__ src, float* __restrict__ dst,
                               const float* __restrict__ k12) {
    const int o = blockIdx.x * 128 + threadIdx.x;   // grid.x = 5
    const int i = blockIdx.y;
    const int c12 = i / 40, a3 = i % 40;
    __shared__ float krow[32];
    if (threadIdx.x < 32) krow[threadIdx.x] = k12[c12 * 32 + threadIdx.x];
    __syncthreads();
    const float* s = src + a3 * DD + o;
    float acc0 = 0.f, acc1 = 0.f;
#pragma unroll 8
    for (int b12 = 0; b12 < 32; b12++) {
        float k = krow[b12];
        acc0 += k * s[b12 * 40 * DD];
        acc1 += k * s[b12 * 40 * DD + 640];
    }
    dst[i * DD + o] = acc0;
    dst[i * DD + o + 640] = acc1;
}
// x -> fp16
__global__ void cvt_x_kernel(const float* __restrict__ x, __half* __restrict__ xh) {
    const size_t i4 = ((size_t)blockIdx.x * 256 + threadIdx.x) * 4;
    float4 v = *reinterpret_cast<const float4*>(x + i4);
    __half2 a = __floats2half2_rn(v.x, v.y);
    __half2 b = __floats2half2_rn(v.z, v.w);
    *reinterpret_cast<uint2*>(xh + i4) =
        make_uint2(*reinterpret_cast<uint32_t*>(&a), *reinterpret_cast<uint32_t*>(&b));
}
// A[k][n] -> fp16(At[n][k])
__global__ void cvt_at_kernel(const float* __restrict__ A, __half* __restrict__ ath) {
    __shared__ float t[32][33];
    const int k0 = blockIdx.x * 32, n0 = blockIdx.y * 32;
    const int tx = threadIdx.x, ty = threadIdx.y;
#pragma unroll
    for (int r = 0; r < 32; r += 8)
        t[ty + r][tx] = A[(k0 + ty + r) * DD + (n0 + tx)];
    __syncthreads();
#pragma unroll
    for (int r = 0; r < 32; r += 8)
        ath[(n0 + ty + r) * DD + (k0 + tx)] = __float2half_rn(t[tx][ty + r]);
}

// ---------------------------------------------------------------------------
// Single-product fp16 HMMA GEMM. CTA tile 128x128, BK=32, 256 threads,
// NSTAGE=5, 2 CTAs/SM, ONE barrier per ktile.
// ---------------------------------------------------------------------------
#define BK 32
#define PADK 40
#define XTB (128 * PADK * 2)        // 10240 B per tile
#define STB (2 * XTB)               // stage: Xh, Ath = 20480 B
#define NSTAGE 5
#define GEMM_SMEM (NSTAGE * STB)    // 102400 B
#define KTILES (DD / BK)            // 40

__device__ __forceinline__ void load_stage_async(
    uint32_t sdst,
    const __half* __restrict__ Xh, const __half* __restrict__ Ath,
    int bm, int bn, int kt, int tid) {
    const int kofs = kt * BK;
#pragma unroll
    for (int i = 0; i < 2; i++) {
        int idx = i * 256 + tid;          // 0..511
        int row = idx >> 2, c = idx & 3;  // 4 x 16B chunks per 64B data row
        uint32_t so = (uint32_t)(row * (PADK * 2) + c * 16);
        size_t gx = (size_t)(bm * 128 + row) * DD + kofs + c * 8;
        size_t ga = (size_t)(bn * 128 + row) * DD + kofs + c * 8;
        CP16(sdst + so,       Xh  + gx);
        CP16(sdst + XTB + so, Ath + ga);
    }
}

__global__ __launch_bounds__(256, 2)
void gemm_hmma_kernel(const __half* __restrict__ Xh,
                      const __half* __restrict__ Ath,
                      float* __restrict__ out) {
    extern __shared__ __align__(128) char smem[];
    const uint32_t sbase = smem_u32(smem);
    const int tid = threadIdx.x, lane = tid & 31, wid = tid >> 5;
    const int warp_m = wid & 3, warp_n = wid >> 2;   // 4 x 2 warps, tile 32x64
    const int bn = blockIdx.x, bm = blockIdx.y;

    float acc[2][8][4];
#pragma unroll
    for (int a = 0; a < 2; a++)
#pragma unroll
        for (int b = 0; b < 8; b++)
#pragma unroll
            for (int c = 0; c < 4; c++) acc[a][b][c] = 0.f;

#pragma unroll
    for (int p = 0; p < 4; p++) {
        load_stage_async(sbase + (uint32_t)p * STB, Xh, Ath, bm, bn, p, tid);
        CP_COMMIT();
    }

    // per-thread ldmatrix lane addressing (byte offsets within a tile)
    const uint32_t a_row = (uint32_t)(warp_m * 32 + (lane & 7) + ((lane >> 3) & 1) * 8);
    const uint32_t a_colb = (uint32_t)(((lane >> 4) & 1) * 8) * 2;
    const uint32_t b_nrow = (uint32_t)(warp_n * 64 + (lane & 7) + ((lane >> 4) & 1) * 8);
    const uint32_t b_kb = (uint32_t)(((lane >> 3) & 1) * 8) * 2;

    for (int kt = 0; kt < KTILES; kt++) {
        CP_WAIT3();
        __syncthreads();   // single barrier per ktile: separates last readers of
                           // the buffer that iteration kt will overwrite (stage
                           // (kt+4)%5, last read in iteration kt-1) from its writers.
        const uint32_t st = sbase + (uint32_t)(kt % NSTAGE) * STB;
        const uint32_t sX = st, sA = st + XTB;
#pragma unroll
        for (int kk = 0; kk < 2; kk++) {
            const uint32_t acol = a_colb + kk * 32;   // kk*16 elems * 2B
            const uint32_t bcol = b_kb + kk * 32;
            uint32_t ax[2][4];
            ldsm_x4(ax[0], sX + a_row * (PADK * 2) + acol);
            ldsm_x4(ax[1], sX + (a_row + 16) * (PADK * 2) + acol);
            uint32_t bb[8][2];
#pragma unroll
            for (int j = 0; j < 4; j++) {
                uint32_t r[4];
                ldsm_x4(r, sA + (b_nrow + j * 16) * (PADK * 2) + bcol);
                bb[2 * j][0] = r[0]; bb[2 * j][1] = r[1];
                bb[2 * j + 1][0] = r[2]; bb[2 * j + 1][1] = r[3];
            }
#pragma unroll
            for (int mi = 0; mi < 2; mi++)
#pragma unroll
                for (int nj = 0; nj < 8; nj++)
                    mma_f16(acc[mi][nj], ax[mi], bb[nj]);
        }
        if (kt + 4 < KTILES)
            load_stage_async(sbase + (uint32_t)((kt + 4) % NSTAGE) * STB,
                             Xh, Ath, bm, bn, kt + 4, tid);
        CP_COMMIT();   // unconditional: keeps wait_group(3) retiring correctly
    }

    // epilogue
    const int er = lane >> 2, ec = (lane & 3) * 2;
#pragma unroll
    for (int mi = 0; mi < 2; mi++) {
        const int row = bm * 128 + warp_m * 32 + mi * 16 + er;
#pragma unroll
        for (int nt = 0; nt < 8; nt++) {
            const int col = bn * 128 + warp_n * 64 + nt * 8 + ec;
            *reinterpret_cast<float2*>(out + (size_t)row * DD + col) =
                make_float2(acc[mi][nt][0], acc[mi][nt][1]);
            *reinterpret_cast<float2*>(out + (size_t)(row + 8) * DD + col) =
                make_float2(acc[mi][nt][2], acc[mi][nt][3]);
        }
    }
}

// ---------------------------------------------------------------------------
extern "C" void kernel_launch(void* const* d_in, const int* in_sizes, int n_in,
                              void* d_out, int out_size) {
    const float* x  = (const float*)d_in[0];
    const float* W  = (const float*)d_in[1];
    const float* k1 = (const float*)d_in[2];
    const float* k2 = (const float*)d_in[3];
    const float* k3 = (const float*)d_in[4];
    float* out = (float*)d_out;

    float *buf0, *buf1, *k12;
    __half *xh, *ath;
    cudaGetSymbolAddress((void**)&buf0, g_buf0);
    cudaGetSymbolAddress((void**)&buf1, g_buf1);
    cudaGetSymbolAddress((void**)&k12, g_k12);
    cudaGetSymbolAddress((void**)&xh, g_Xh);
    cudaGetSymbolAddress((void**)&ath, g_Ath);

    {
        size_t n4 = (size_t)MROWS * DD / 4;
        cvt_x_kernel<<<(unsigned)(n4 / 256), 256>>>(x, xh);
    }
    kron12_kernel<<<1, 1024>>>(k1, k2, k12);
    {
        dim3 grid(DD / 32, DD / 32), block(32, 8);
        transpose_kernel<<<grid, block>>>(W, buf0);
    }
    {
        dim3 grid(5, DD), block(128);
        stage3_kernel<<<grid, block>>>(buf0, buf1, k3);   // buf1 = T1
        stage12_kernel<<<grid, block>>>(buf1, buf0, k12); // buf0 = A
    }
    {
        dim3 grid(DD / 32, DD / 32), block(32, 8);
        cvt_at_kernel<<<grid, block>>>(buf0, ath);
    }
    {
        static bool attr_set = false;
        if (!attr_set) {
            cudaFuncSetAttribute(gemm_hmma_kernel,
                                 cudaFuncAttributeMaxDynamicSharedMemorySize, GEMM_SMEM);
            attr_set = true;
        }
        dim3 grid(DD / 128, MROWS / 128);   // (10, 128)
        gemm_hmma_kernel<<<grid, 256, GEMM_SMEM>>>(xh, ath, out);
    }
}